// round 2
// baseline (speedup 1.0000x reference)
#include <cuda_runtime.h>

#define NN 50000
#define EE 500000
#define DD 384
#define BB 64
#define HMAX 6
#define ETOT (EE + NN)

// ---------------- scratch (static device allocations) ----------------
__device__ __align__(16) float g_h[(size_t)NN * DD];    // projected features
__device__ __align__(16) float g_out[(size_t)NN * DD];  // aggregated output
__device__ __align__(16) float g_x[(size_t)NN * DD];    // layer input (x1, x2)
__device__ float g_ssrc[NN * HMAX];
__device__ float g_sdst[NN * HMAX];
__device__ float g_denom[NN * HMAX];
__device__ float g_w[(size_t)ETOT * HMAX];
__device__ int g_off[BB + 2];

// ---------------- SGEMM: C[M,384] = A[M,384] * W[384,384] -> g_h ----------------
__global__ void sgemm64(const float* __restrict__ A, const float* __restrict__ B) {
    __shared__ float As[16][65];
    __shared__ float Bs[16][65];
    int tid = threadIdx.x;
    int tx = tid & 15, ty = tid >> 4;
    int n0 = blockIdx.x * 64;
    int m0 = blockIdx.y * 64;
    float acc[4][4] = {};
    int lr = tid >> 2;   // 0..63: A tile row
    int lq = tid & 3;    // 0..3:  A tile float4 col
    int bk = tid >> 4;   // 0..15: B tile row
    int bc = tid & 15;   // 0..15: B tile float4 col
    for (int k0 = 0; k0 < 384; k0 += 16) {
        float4 av = make_float4(0.f, 0.f, 0.f, 0.f);
        int row = m0 + lr;
        if (row < NN) av = *(const float4*)(A + (size_t)row * 384 + k0 + lq * 4);
        As[lq * 4 + 0][lr] = av.x;
        As[lq * 4 + 1][lr] = av.y;
        As[lq * 4 + 2][lr] = av.z;
        As[lq * 4 + 3][lr] = av.w;
        float4 bv = *(const float4*)(B + (size_t)(k0 + bk) * 384 + n0 + bc * 4);
        Bs[bk][bc * 4 + 0] = bv.x;
        Bs[bk][bc * 4 + 1] = bv.y;
        Bs[bk][bc * 4 + 2] = bv.z;
        Bs[bk][bc * 4 + 3] = bv.w;
        __syncthreads();
#pragma unroll
        for (int kk = 0; kk < 16; kk++) {
            float a4[4], b4[4];
#pragma unroll
            for (int i = 0; i < 4; i++) a4[i] = As[kk][ty * 4 + i];
#pragma unroll
            for (int j = 0; j < 4; j++) b4[j] = Bs[kk][tx * 4 + j];
#pragma unroll
            for (int i = 0; i < 4; i++)
#pragma unroll
                for (int j = 0; j < 4; j++) acc[i][j] += a4[i] * b4[j];
        }
        __syncthreads();
    }
#pragma unroll
    for (int i = 0; i < 4; i++) {
        int row = m0 + ty * 4 + i;
        if (row < NN) {
#pragma unroll
            for (int j = 0; j < 4; j++)
                g_h[(size_t)row * 384 + n0 + tx * 4 + j] = acc[i][j];
        }
    }
}

// ---------------- attention logits: s_src[n,h], s_dst[n,h] ----------------
template <int H, int C>
__global__ void s_kernel(const float* __restrict__ a_src, const float* __restrict__ a_dst) {
    int gw = (blockIdx.x * blockDim.x + threadIdx.x) >> 5;
    int lane = threadIdx.x & 31;
    int n = gw / H, hh = gw % H;
    if (n >= NN) return;
    float ss = 0.f, sd = 0.f;
    for (int c = lane; c < C; c += 32) {
        float v = g_h[(size_t)n * DD + hh * C + c];
        ss += v * a_src[hh * C + c];
        sd += v * a_dst[hh * C + c];
    }
#pragma unroll
    for (int o = 16; o; o >>= 1) {
        ss += __shfl_down_sync(0xffffffffu, ss, o);
        sd += __shfl_down_sync(0xffffffffu, sd, o);
    }
    if (lane == 0) {
        g_ssrc[n * H + hh] = ss;
        g_sdst[n * H + hh] = sd;
    }
}

// ---------------- per-edge exp weights + softmax denominators ----------------
template <int H>
__global__ void edge_w_kernel(const int* __restrict__ esrc, const int* __restrict__ edst) {
    int e = blockIdx.x * blockDim.x + threadIdx.x;
    if (e >= ETOT) return;
    int s, d;
    if (e < EE) {
        s = esrc[e];
        d = edst[e];
    } else {
        s = d = e - EE;
    }
#pragma unroll
    for (int hh = 0; hh < H; hh++) {
        float t = g_ssrc[s * H + hh] + g_sdst[d * H + hh];
        t = t > 0.f ? t : 0.2f * t;
        float wv = __expf(t);
        g_w[(size_t)e * H + hh] = wv;
        atomicAdd(&g_denom[d * H + hh], wv);
    }
}

// ---------------- weighted scatter aggregation (warp per edge) ----------------
template <int H, int C>
__global__ void aggregate_kernel(const int* __restrict__ esrc, const int* __restrict__ edst) {
    int gw = (blockIdx.x * blockDim.x + threadIdx.x) >> 5;
    int lane = threadIdx.x & 31;
    if (gw >= ETOT) return;
    int s, d;
    if (gw < EE) {
        s = esrc[gw];
        d = edst[gw];
    } else {
        s = d = gw - EE;
    }
    float a = 0.f;
    if (lane < H) a = g_w[(size_t)gw * H + lane] / (g_denom[d * H + lane] + 1e-16f);
    const float4* hs = (const float4*)(g_h + (size_t)s * DD);
    float* op = g_out + (size_t)d * DD;
#pragma unroll
    for (int q = 0; q < 3; q++) {
        int qi = lane + q * 32;
        float4 v = hs[qi];
        int c0 = qi * 4;
        float alpha = __shfl_sync(0xffffffffu, a, c0 / C);
        atomicAdd(op + c0 + 0, alpha * v.x);
        atomicAdd(op + c0 + 1, alpha * v.y);
        atomicAdd(op + c0 + 2, alpha * v.z);
        atomicAdd(op + c0 + 3, alpha * v.w);
    }
}

// ---------------- bias + LayerNorm + ReLU -> g_x ----------------
__global__ void ln_relu_kernel(const float* __restrict__ b, const float* __restrict__ gam,
                               const float* __restrict__ bet) {
    int n = blockIdx.x;
    int t = threadIdx.x;  // 128 threads
    float v[3];
    float s = 0.f;
#pragma unroll
    for (int i = 0; i < 3; i++) {
        int c = t + i * 128;
        v[i] = g_out[(size_t)n * DD + c] + b[c];
        s += v[i];
    }
    __shared__ float red[4];
    __shared__ float red2[4];
#pragma unroll
    for (int o = 16; o; o >>= 1) s += __shfl_down_sync(0xffffffffu, s, o);
    if ((t & 31) == 0) red[t >> 5] = s;
    __syncthreads();
    float mu = (red[0] + red[1] + red[2] + red[3]) * (1.f / 384.f);
    float d2 = 0.f;
#pragma unroll
    for (int i = 0; i < 3; i++) {
        float dd = v[i] - mu;
        d2 += dd * dd;
    }
#pragma unroll
    for (int o = 16; o; o >>= 1) d2 += __shfl_down_sync(0xffffffffu, d2, o);
    if ((t & 31) == 0) red2[t >> 5] = d2;
    __syncthreads();
    float var = (red2[0] + red2[1] + red2[2] + red2[3]) * (1.f / 384.f);
    float rstd = rsqrtf(var + 1e-5f);
#pragma unroll
    for (int i = 0; i < 3; i++) {
        int c = t + i * 128;
        float y = (v[i] - mu) * rstd * gam[c] + bet[c];
        g_x[(size_t)n * DD + c] = y > 0.f ? y : 0.f;
    }
}

// ---------------- batch offsets (batch is sorted) ----------------
__global__ void offsets_kernel(const int* __restrict__ batch) {
    int g = threadIdx.x;
    if (g > BB) return;
    int lo = 0, hi = NN;
    while (lo < hi) {
        int mid = (lo + hi) >> 1;
        if (batch[mid] < g)
            lo = mid + 1;
        else
            hi = mid;
    }
    g_off[g] = lo;
}

// ---------------- residual + relu(bias) + mean pool ----------------
__global__ void pool_kernel(const float* __restrict__ x0, const float* __restrict__ b3,
                            float* __restrict__ out) {
    int g = blockIdx.x, c = threadIdx.x;  // 384 threads
    int s = g_off[g], e = g_off[g + 1];
    float bias = b3[c], acc = 0.f;
    for (int n = s; n < e; n++) {
        float v = g_out[(size_t)n * DD + c] + bias;
        acc += x0[(size_t)n * DD + c] + (v > 0.f ? v : 0.f);
    }
    int cnt = e - s;
    out[g * DD + c] = acc / (float)(cnt > 0 ? cnt : 1);
}

// ---------------- host launch ----------------
extern "C" void kernel_launch(void* const* d_in, const int* in_sizes, int n_in,
                              void* d_out, int out_size) {
    const float* x = (const float*)d_in[0];
    const int* ei = (const int*)d_in[1];
    const int* batch = (const int*)d_in[2];
    const float* W1 = (const float*)d_in[3];
    const float* a1s = (const float*)d_in[4];
    const float* a1d = (const float*)d_in[5];
    const float* b1 = (const float*)d_in[6];
    const float* g1 = (const float*)d_in[7];
    const float* be1 = (const float*)d_in[8];
    const float* W2 = (const float*)d_in[9];
    const float* a2s = (const float*)d_in[10];
    const float* a2d = (const float*)d_in[11];
    const float* b2 = (const float*)d_in[12];
    const float* g2 = (const float*)d_in[13];
    const float* be2 = (const float*)d_in[14];
    const float* W3 = (const float*)d_in[15];
    const float* a3s = (const float*)d_in[16];
    const float* a3d = (const float*)d_in[17];
    const float* b3 = (const float*)d_in[18];
    float* out = (float*)d_out;

    void* pv;
    cudaGetSymbolAddress(&pv, g_denom);
    float* denomp = (float*)pv;
    cudaGetSymbolAddress(&pv, g_out);
    float* outp = (float*)pv;
    cudaGetSymbolAddress(&pv, g_x);
    float* xp = (float*)pv;

    const int* esrc = ei;
    const int* edst = ei + EE;
    dim3 gemm_grid(6, (NN + 63) / 64);
    int ew_blocks = (ETOT + 255) / 256;
    int ag_blocks = (ETOT + 7) / 8;

    // ---- layer 1 (H=4, C=96) ----
    cudaMemsetAsync(denomp, 0, NN * HMAX * sizeof(float));
    cudaMemsetAsync(outp, 0, (size_t)NN * DD * sizeof(float));
    sgemm64<<<gemm_grid, 256>>>(x, W1);
    s_kernel<4, 96><<<(NN * 4 + 7) / 8, 256>>>(a1s, a1d);
    edge_w_kernel<4><<<ew_blocks, 256>>>(esrc, edst);
    aggregate_kernel<4, 96><<<ag_blocks, 256>>>(esrc, edst);
    ln_relu_kernel<<<NN, 128>>>(b1, g1, be1);

    // ---- layer 2 (H=4, C=96) ----
    cudaMemsetAsync(denomp, 0, NN * HMAX * sizeof(float));
    cudaMemsetAsync(outp, 0, (size_t)NN * DD * sizeof(float));
    sgemm64<<<gemm_grid, 256>>>(xp, W2);
    s_kernel<4, 96><<<(NN * 4 + 7) / 8, 256>>>(a2s, a2d);
    edge_w_kernel<4><<<ew_blocks, 256>>>(esrc, edst);
    aggregate_kernel<4, 96><<<ag_blocks, 256>>>(esrc, edst);
    ln_relu_kernel<<<NN, 128>>>(b2, g2, be2);

    // ---- layer 3 (H=6, C=64) ----
    cudaMemsetAsync(denomp, 0, NN * HMAX * sizeof(float));
    cudaMemsetAsync(outp, 0, (size_t)NN * DD * sizeof(float));
    sgemm64<<<gemm_grid, 256>>>(xp, W3);
    s_kernel<6, 64><<<(NN * 6 + 7) / 8, 256>>>(a3s, a3d);
    edge_w_kernel<6><<<ew_blocks, 256>>>(esrc, edst);
    aggregate_kernel<6, 64><<<ag_blocks, 256>>>(esrc, edst);

    // ---- pooling ----
    offsets_kernel<<<1, 128>>>(batch);
    pool_kernel<<<BB, DD>>>(x, b3, out);
}

// round 3
// speedup vs baseline: 2.5933x; 2.5933x over previous
#include <cuda_runtime.h>

#define NN 50000
#define EE 500000
#define DD 384
#define BB 64
#define HMAX 6
#define ETOT (EE + NN)

// ---------------- scratch (static device allocations) ----------------
__device__ __align__(16) float g_h[(size_t)NN * DD];    // projected features
__device__ __align__(16) float g_out[(size_t)NN * DD];  // aggregated output
__device__ __align__(16) float g_x[(size_t)NN * DD];    // layer input (x1, x2)
__device__ float g_ssrc[NN * HMAX];
__device__ float g_sdst[NN * HMAX];
__device__ int g_deg[NN];
__device__ int g_cur[NN];
__device__ int g_csr_off[NN + 1];
__device__ int g_csr_src[ETOT];
__device__ int g_off[BB + 2];

// ---------------- CSR build ----------------
__global__ void count_kernel(const int* __restrict__ edst) {
    int e = blockIdx.x * blockDim.x + threadIdx.x;
    if (e >= ETOT) return;
    int d = (e < EE) ? edst[e] : (e - EE);
    atomicAdd(&g_deg[d], 1);
}

__global__ void scan_kernel() {
    // one block, 1024 threads: exclusive scan of g_deg -> g_csr_off
    const int T = 1024;
    const int CH = (NN + T - 1) / T;  // 49
    __shared__ int warp_sums[32];
    int t = threadIdx.x;
    int base = t * CH;
    int s = 0;
    for (int i = 0; i < CH; i++) {
        int idx = base + i;
        if (idx < NN) s += g_deg[idx];
    }
    int lane = t & 31, wid = t >> 5;
    int v = s;
#pragma unroll
    for (int o = 1; o < 32; o <<= 1) {
        int u = __shfl_up_sync(0xffffffffu, v, o);
        if (lane >= o) v += u;
    }
    if (lane == 31) warp_sums[wid] = v;
    __syncthreads();
    if (wid == 0) {
        int w = warp_sums[lane];
#pragma unroll
        for (int o = 1; o < 32; o <<= 1) {
            int u = __shfl_up_sync(0xffffffffu, w, o);
            if (lane >= o) w += u;
        }
        warp_sums[lane] = w;
    }
    __syncthreads();
    int excl = v - s + (wid > 0 ? warp_sums[wid - 1] : 0);
    int run = excl;
    for (int i = 0; i < CH; i++) {
        int idx = base + i;
        if (idx < NN) {
            g_csr_off[idx] = run;
            run += g_deg[idx];
        }
    }
    if (t == 0) g_csr_off[NN] = ETOT;
}

__global__ void fill_kernel(const int* __restrict__ esrc, const int* __restrict__ edst) {
    int e = blockIdx.x * blockDim.x + threadIdx.x;
    if (e >= ETOT) return;
    int s, d;
    if (e < EE) {
        s = esrc[e];
        d = edst[e];
    } else {
        s = d = e - EE;
    }
    int slot = g_csr_off[d] + atomicAdd(&g_cur[d], 1);
    g_csr_src[slot] = s;
}

// ---------------- SGEMM v2: C[M,384] = A[M,384] * W[384,384] -> g_h ----------------
// 128x64 tile, BK=16, 256 threads, 8x4 acc per thread
__global__ __launch_bounds__(256) void sgemm_v2(const float* __restrict__ A,
                                                const float* __restrict__ B) {
    __shared__ float As[16 * 132];  // As[k][m], stride 132
    __shared__ float Bs[16 * 68];   // Bs[k][n], stride 68
    int tid = threadIdx.x;
    int tx = tid & 15, ty = tid >> 4;
    int m0 = blockIdx.y * 128;
    int n0 = blockIdx.x * 64;
    int ar = tid >> 2;  // 0..63
    int ac = tid & 3;   // float4 col in A k-slab
    int br = tid >> 4;  // 0..15
    int bc = tid & 15;  // float4 col in B tile
    float acc[8][4] = {};
    for (int k0 = 0; k0 < 384; k0 += 16) {
        float4 a0 = make_float4(0.f, 0.f, 0.f, 0.f);
        float4 a1 = make_float4(0.f, 0.f, 0.f, 0.f);
        int r0 = m0 + ar, r1 = m0 + ar + 64;
        if (r0 < NN) a0 = *(const float4*)(A + (size_t)r0 * 384 + k0 + ac * 4);
        if (r1 < NN) a1 = *(const float4*)(A + (size_t)r1 * 384 + k0 + ac * 4);
        As[(ac * 4 + 0) * 132 + ar] = a0.x;
        As[(ac * 4 + 1) * 132 + ar] = a0.y;
        As[(ac * 4 + 2) * 132 + ar] = a0.z;
        As[(ac * 4 + 3) * 132 + ar] = a0.w;
        As[(ac * 4 + 0) * 132 + ar + 64] = a1.x;
        As[(ac * 4 + 1) * 132 + ar + 64] = a1.y;
        As[(ac * 4 + 2) * 132 + ar + 64] = a1.z;
        As[(ac * 4 + 3) * 132 + ar + 64] = a1.w;
        float4 bv = *(const float4*)(B + (size_t)(k0 + br) * 384 + n0 + bc * 4);
        *(float4*)&Bs[br * 68 + bc * 4] = bv;
        __syncthreads();
#pragma unroll
        for (int kk = 0; kk < 16; kk++) {
            float4 a04 = *(float4*)&As[kk * 132 + ty * 8];
            float4 a14 = *(float4*)&As[kk * 132 + ty * 8 + 4];
            float4 b4 = *(float4*)&Bs[kk * 68 + tx * 4];
            float am[8] = {a04.x, a04.y, a04.z, a04.w, a14.x, a14.y, a14.z, a14.w};
            float bn[4] = {b4.x, b4.y, b4.z, b4.w};
#pragma unroll
            for (int i = 0; i < 8; i++)
#pragma unroll
                for (int j = 0; j < 4; j++) acc[i][j] += am[i] * bn[j];
        }
        __syncthreads();
    }
#pragma unroll
    for (int i = 0; i < 8; i++) {
        int row = m0 + ty * 8 + i;
        if (row < NN) {
            float4 v = make_float4(acc[i][0], acc[i][1], acc[i][2], acc[i][3]);
            *(float4*)(g_h + (size_t)row * 384 + n0 + tx * 4) = v;
        }
    }
}

// ---------------- attention logits: s_src[n,h], s_dst[n,h] ----------------
template <int H, int C>
__global__ void s_kernel(const float* __restrict__ a_src, const float* __restrict__ a_dst) {
    int gw = (blockIdx.x * blockDim.x + threadIdx.x) >> 5;
    int lane = threadIdx.x & 31;
    int n = gw / H, hh = gw % H;
    if (n >= NN) return;
    float ss = 0.f, sd = 0.f;
    for (int c = lane; c < C; c += 32) {
        float v = g_h[(size_t)n * DD + hh * C + c];
        ss += v * a_src[hh * C + c];
        sd += v * a_dst[hh * C + c];
    }
#pragma unroll
    for (int o = 16; o; o >>= 1) {
        ss += __shfl_down_sync(0xffffffffu, ss, o);
        sd += __shfl_down_sync(0xffffffffu, sd, o);
    }
    if (lane == 0) {
        g_ssrc[n * H + hh] = ss;
        g_sdst[n * H + hh] = sd;
    }
}

// ---------------- fused softmax + gather aggregation (block per dst) ----------------
// out[d,c] = sum_e w_e * h[src_e,c] / (sum_e w_e + 1e-16), w_e = exp(lrelu(...))
template <int H, int C>
__global__ __launch_bounds__(128) void gather_kernel() {
    int d = blockIdx.x;
    int t = threadIdx.x;  // 128
    int beg = g_csr_off[d], end = g_csr_off[d + 1];
    const int c0 = t, c1 = t + 128, c2 = t + 256;
    const int h0 = c0 / C, h1 = c1 / C, h2 = c2 / C;
    float sd0 = g_sdst[d * H + h0];
    float sd1 = g_sdst[d * H + h1];
    float sd2 = g_sdst[d * H + h2];
    float n0 = 0.f, n1 = 0.f, n2 = 0.f;
    float e0 = 0.f, e1 = 0.f, e2 = 0.f;
    for (int p = beg; p < end; p++) {
        int s = g_csr_src[p];
        const float* hr = g_h + (size_t)s * DD;
        float t0 = g_ssrc[s * H + h0] + sd0;
        float t1 = g_ssrc[s * H + h1] + sd1;
        float t2 = g_ssrc[s * H + h2] + sd2;
        t0 = t0 > 0.f ? t0 : 0.2f * t0;
        t1 = t1 > 0.f ? t1 : 0.2f * t1;
        t2 = t2 > 0.f ? t2 : 0.2f * t2;
        float w0 = __expf(t0), w1 = __expf(t1), w2 = __expf(t2);
        n0 += w0 * hr[c0];
        n1 += w1 * hr[c1];
        n2 += w2 * hr[c2];
        e0 += w0;
        e1 += w1;
        e2 += w2;
    }
    float* o = g_out + (size_t)d * DD;
    o[c0] = n0 / (e0 + 1e-16f);
    o[c1] = n1 / (e1 + 1e-16f);
    o[c2] = n2 / (e2 + 1e-16f);
}

// ---------------- bias + LayerNorm + ReLU -> g_x ----------------
__global__ void ln_relu_kernel(const float* __restrict__ b, const float* __restrict__ gam,
                               const float* __restrict__ bet) {
    int n = blockIdx.x;
    int t = threadIdx.x;  // 128 threads
    float v[3];
    float s = 0.f;
#pragma unroll
    for (int i = 0; i < 3; i++) {
        int c = t + i * 128;
        v[i] = g_out[(size_t)n * DD + c] + b[c];
        s += v[i];
    }
    __shared__ float red[4];
    __shared__ float red2[4];
#pragma unroll
    for (int o = 16; o; o >>= 1) s += __shfl_down_sync(0xffffffffu, s, o);
    if ((t & 31) == 0) red[t >> 5] = s;
    __syncthreads();
    float mu = (red[0] + red[1] + red[2] + red[3]) * (1.f / 384.f);
    float d2 = 0.f;
#pragma unroll
    for (int i = 0; i < 3; i++) {
        float dd = v[i] - mu;
        d2 += dd * dd;
    }
#pragma unroll
    for (int o = 16; o; o >>= 1) d2 += __shfl_down_sync(0xffffffffu, d2, o);
    if ((t & 31) == 0) red2[t >> 5] = d2;
    __syncthreads();
    float var = (red2[0] + red2[1] + red2[2] + red2[3]) * (1.f / 384.f);
    float rstd = rsqrtf(var + 1e-5f);
#pragma unroll
    for (int i = 0; i < 3; i++) {
        int c = t + i * 128;
        float y = (v[i] - mu) * rstd * gam[c] + bet[c];
        g_x[(size_t)n * DD + c] = y > 0.f ? y : 0.f;
    }
}

// ---------------- batch offsets (batch is sorted) ----------------
__global__ void offsets_kernel(const int* __restrict__ batch) {
    int g = threadIdx.x;
    if (g > BB) return;
    int lo = 0, hi = NN;
    while (lo < hi) {
        int mid = (lo + hi) >> 1;
        if (batch[mid] < g)
            lo = mid + 1;
        else
            hi = mid;
    }
    g_off[g] = lo;
}

// ---------------- residual + relu(bias) + mean pool ----------------
__global__ void pool_kernel(const float* __restrict__ x0, const float* __restrict__ b3,
                            float* __restrict__ out) {
    int g = blockIdx.x, c = threadIdx.x;  // 384 threads
    int s = g_off[g], e = g_off[g + 1];
    float bias = b3[c], acc = 0.f;
    for (int n = s; n < e; n++) {
        float v = g_out[(size_t)n * DD + c] + bias;
        acc += x0[(size_t)n * DD + c] + (v > 0.f ? v : 0.f);
    }
    int cnt = e - s;
    out[g * DD + c] = acc / (float)(cnt > 0 ? cnt : 1);
}

// ---------------- host launch ----------------
extern "C" void kernel_launch(void* const* d_in, const int* in_sizes, int n_in,
                              void* d_out, int out_size) {
    const float* x = (const float*)d_in[0];
    const int* ei = (const int*)d_in[1];
    const int* batch = (const int*)d_in[2];
    const float* W1 = (const float*)d_in[3];
    const float* a1s = (const float*)d_in[4];
    const float* a1d = (const float*)d_in[5];
    const float* b1 = (const float*)d_in[6];
    const float* g1 = (const float*)d_in[7];
    const float* be1 = (const float*)d_in[8];
    const float* W2 = (const float*)d_in[9];
    const float* a2s = (const float*)d_in[10];
    const float* a2d = (const float*)d_in[11];
    const float* b2 = (const float*)d_in[12];
    const float* g2 = (const float*)d_in[13];
    const float* be2 = (const float*)d_in[14];
    const float* W3 = (const float*)d_in[15];
    const float* a3s = (const float*)d_in[16];
    const float* a3d = (const float*)d_in[17];
    const float* b3 = (const float*)d_in[18];
    float* out = (float*)d_out;

    void* pv;
    cudaGetSymbolAddress(&pv, g_deg);
    int* degp = (int*)pv;
    cudaGetSymbolAddress(&pv, g_cur);
    int* curp = (int*)pv;
    cudaGetSymbolAddress(&pv, g_x);
    float* xp = (float*)pv;

    const int* esrc = ei;
    const int* edst = ei + EE;
    dim3 gemm_grid(6, (NN + 127) / 128);
    int eb = (ETOT + 255) / 256;

    // ---- CSR build (by dst), reused across all 3 layers ----
    cudaMemsetAsync(degp, 0, NN * sizeof(int));
    count_kernel<<<eb, 256>>>(edst);
    scan_kernel<<<1, 1024>>>();
    cudaMemsetAsync(curp, 0, NN * sizeof(int));
    fill_kernel<<<eb, 256>>>(esrc, edst);

    // ---- layer 1 (H=4, C=96) ----
    sgemm_v2<<<gemm_grid, 256>>>(x, W1);
    s_kernel<4, 96><<<(NN * 4 + 7) / 8, 256>>>(a1s, a1d);
    gather_kernel<4, 96><<<NN, 128>>>();
    ln_relu_kernel<<<NN, 128>>>(b1, g1, be1);

    // ---- layer 2 (H=4, C=96) ----
    sgemm_v2<<<gemm_grid, 256>>>(xp, W2);
    s_kernel<4, 96><<<(NN * 4 + 7) / 8, 256>>>(a2s, a2d);
    gather_kernel<4, 96><<<NN, 128>>>();
    ln_relu_kernel<<<NN, 128>>>(b2, g2, be2);

    // ---- layer 3 (H=6, C=64) ----
    sgemm_v2<<<gemm_grid, 256>>>(xp, W3);
    s_kernel<6, 64><<<(NN * 6 + 7) / 8, 256>>>(a3s, a3d);
    gather_kernel<6, 64><<<NN, 128>>>();

    // ---- pooling ----
    offsets_kernel<<<1, 128>>>(batch);
    pool_kernel<<<BB, DD>>>(x, b3, out);
}

// round 5
// speedup vs baseline: 4.2909x; 1.6546x over previous
#include <cuda_runtime.h>
#include <cstdint>

#define NN 50000
#define EE 500000
#define DD 384
#define BB 64
#define HMAX 6
#define ETOT (EE + NN)

// ---------------- scratch (static device allocations) ----------------
__device__ __align__(16) float g_h[(size_t)NN * DD];    // projected features
__device__ __align__(16) float g_out[(size_t)NN * DD];  // aggregated output
__device__ __align__(16) float g_x[(size_t)NN * DD];    // layer input (x1, x2)
__device__ float g_ssrc[NN * HMAX];
__device__ float g_sdst[NN * HMAX];
__device__ int g_deg[NN];
__device__ int g_cur[NN];
__device__ int g_csr_off[NN + 1];
__device__ int g_csr_src[ETOT];
__device__ int g_off[BB + 2];

// ================= helpers =================
__device__ __forceinline__ uint32_t smem_u32(const void* p) {
    uint32_t a;
    asm("{ .reg .u64 t; cvta.to.shared.u64 t, %1; cvt.u32.u64 %0, t; }" : "=r"(a) : "l"(p));
    return a;
}
#define CP16(sa, g) asm volatile("cp.async.cg.shared.global [%0], [%1], 16;" ::"r"(sa), "l"(g))
#define CP_COMMIT() asm volatile("cp.async.commit_group;" ::: "memory")

__device__ __forceinline__ uint32_t to_tf32(float x) {
    uint32_t u;
    asm("cvt.rna.tf32.f32 %0, %1;" : "=r"(u) : "f"(x));
    return u;
}
__device__ __forceinline__ void mma_tf32(float* d, uint32_t a0, uint32_t a1, uint32_t a2,
                                         uint32_t a3, uint32_t b0, uint32_t b1) {
    asm volatile(
        "mma.sync.aligned.m16n8k8.row.col.f32.tf32.tf32.f32 "
        "{%0,%1,%2,%3}, {%4,%5,%6,%7}, {%8,%9}, {%0,%1,%2,%3};"
        : "+f"(d[0]), "+f"(d[1]), "+f"(d[2]), "+f"(d[3])
        : "r"(a0), "r"(a1), "r"(a2), "r"(a3), "r"(b0), "r"(b1));
}

// ================= tf32 mma.sync GEMM: g_h[M,384] = A[M,384] @ W[384,384] =================
// grid (6, 391), 256 threads. CTA tile 128(M) x 64(N), K chunks of 32, double-buffered cp.async.
// smem per stage: As[128][36] + Bs[32][72]  (floats), conflict-free fragment loads.
#define GEMM_SMEM (2 * 6912 * 4)

__global__ __launch_bounds__(256) void gemm_mma(const float* __restrict__ A,
                                                const float* __restrict__ W) {
    extern __shared__ float sm[];
    int tid = threadIdx.x;
    int m0 = blockIdx.y * 128, n0 = blockIdx.x * 64;
    int lane = tid & 31, wid = tid >> 5;
    int wm = wid & 3, wn = wid >> 2;   // 4 x 2 warp grid, warp tile 32x32
    int r = lane >> 2, kq = lane & 3;  // groupID, threadID_in_group

    float acc[2][4][4];
#pragma unroll
    for (int i = 0; i < 2; i++)
#pragma unroll
        for (int j = 0; j < 4; j++)
#pragma unroll
            for (int q = 0; q < 4; q++) acc[i][j][q] = 0.f;

    auto issue = [&](int c, int st) {
        float* As = sm + st * 6912;
        float* Bs = As + 4608;
        int k0 = c * 32;
#pragma unroll
        for (int i = 0; i < 4; i++) {
            int idx = i * 256 + tid;
            int m = idx >> 3, seg = idx & 7;
            int row = m0 + m;
            if (row > NN - 1) row = NN - 1;
            CP16(smem_u32(As + m * 36 + seg * 4), A + (size_t)row * DD + k0 + seg * 4);
        }
#pragma unroll
        for (int i = 0; i < 2; i++) {
            int idx = i * 256 + tid;
            int kr = idx >> 4, seg = idx & 15;
            CP16(smem_u32(Bs + kr * 72 + seg * 4), W + (size_t)(k0 + kr) * DD + n0 + seg * 4);
        }
        CP_COMMIT();
    };

    issue(0, 0);
    for (int c = 0; c < 12; c++) {
        int st = c & 1;
        if (c < 11) {
            issue(c + 1, st ^ 1);
            asm volatile("cp.async.wait_group 1;" ::: "memory");
        } else {
            asm volatile("cp.async.wait_group 0;" ::: "memory");
        }
        __syncthreads();
        const float* As = sm + st * 6912;
        const float* Bs = As + 4608;
#pragma unroll
        for (int ks = 0; ks < 4; ks++) {
            int kk = ks * 8;
            uint32_t a[2][4], b[4][2];
#pragma unroll
            for (int mi = 0; mi < 2; mi++) {
                int row = wm * 32 + mi * 16 + r;
                a[mi][0] = to_tf32(As[row * 36 + kk + kq]);
                a[mi][1] = to_tf32(As[(row + 8) * 36 + kk + kq]);
                a[mi][2] = to_tf32(As[row * 36 + kk + kq + 4]);
                a[mi][3] = to_tf32(As[(row + 8) * 36 + kk + kq + 4]);
            }
#pragma unroll
            for (int j = 0; j < 4; j++) {
                int col = wn * 32 + j * 8 + r;
                b[j][0] = to_tf32(Bs[(kk + kq) * 72 + col]);
                b[j][1] = to_tf32(Bs[(kk + kq + 4) * 72 + col]);
            }
#pragma unroll
            for (int mi = 0; mi < 2; mi++)
#pragma unroll
                for (int j = 0; j < 4; j++)
                    mma_tf32(acc[mi][j], a[mi][0], a[mi][1], a[mi][2], a[mi][3], b[j][0], b[j][1]);
        }
        __syncthreads();
    }

    // epilogue: direct float2 stores
#pragma unroll
    for (int mi = 0; mi < 2; mi++) {
#pragma unroll
        for (int j = 0; j < 4; j++) {
            int row = m0 + wm * 32 + mi * 16 + r;
            int col = n0 + wn * 32 + j * 8 + kq * 2;
            if (row < NN)
                *(float2*)&g_h[(size_t)row * DD + col] = make_float2(acc[mi][j][0], acc[mi][j][1]);
            if (row + 8 < NN)
                *(float2*)&g_h[(size_t)(row + 8) * DD + col] =
                    make_float2(acc[mi][j][2], acc[mi][j][3]);
        }
    }
}

// ---------------- CSR build ----------------
__global__ void count_kernel(const int* __restrict__ edst) {
    int e = blockIdx.x * blockDim.x + threadIdx.x;
    if (e >= ETOT) return;
    int d = (e < EE) ? edst[e] : (e - EE);
    atomicAdd(&g_deg[d], 1);
}

__global__ void scan_kernel() {
    const int T = 1024;
    const int CH = (NN + T - 1) / T;
    __shared__ int warp_sums[32];
    int t = threadIdx.x;
    int base = t * CH;
    int s = 0;
    for (int i = 0; i < CH; i++) {
        int idx = base + i;
        if (idx < NN) s += g_deg[idx];
    }
    int lane = t & 31, wid = t >> 5;
    int v = s;
#pragma unroll
    for (int o = 1; o < 32; o <<= 1) {
        int u = __shfl_up_sync(0xffffffffu, v, o);
        if (lane >= o) v += u;
    }
    if (lane == 31) warp_sums[wid] = v;
    __syncthreads();
    if (wid == 0) {
        int w = warp_sums[lane];
#pragma unroll
        for (int o = 1; o < 32; o <<= 1) {
            int u = __shfl_up_sync(0xffffffffu, w, o);
            if (lane >= o) w += u;
        }
        warp_sums[lane] = w;
    }
    __syncthreads();
    int excl = v - s + (wid > 0 ? warp_sums[wid - 1] : 0);
    int run = excl;
    for (int i = 0; i < CH; i++) {
        int idx = base + i;
        if (idx < NN) {
            g_csr_off[idx] = run;
            run += g_deg[idx];
        }
    }
    if (t == 0) g_csr_off[NN] = ETOT;
}

__global__ void fill_kernel(const int* __restrict__ esrc, const int* __restrict__ edst) {
    int e = blockIdx.x * blockDim.x + threadIdx.x;
    if (e >= ETOT) return;
    int s, d;
    if (e < EE) {
        s = esrc[e];
        d = edst[e];
    } else {
        s = d = e - EE;
    }
    int slot = g_csr_off[d] + atomicAdd(&g_cur[d], 1);
    g_csr_src[slot] = s;
}

// ---------------- attention logits ----------------
template <int H, int C>
__global__ void s_kernel(const float* __restrict__ a_src, const float* __restrict__ a_dst) {
    int gw = (blockIdx.x * blockDim.x + threadIdx.x) >> 5;
    int lane = threadIdx.x & 31;
    int n = gw / H, hh = gw % H;
    if (n >= NN) return;
    float ss = 0.f, sd = 0.f;
    for (int c = lane; c < C; c += 32) {
        float v = g_h[(size_t)n * DD + hh * C + c];
        ss += v * a_src[hh * C + c];
        sd += v * a_dst[hh * C + c];
    }
#pragma unroll
    for (int o = 16; o; o >>= 1) {
        ss += __shfl_down_sync(0xffffffffu, ss, o);
        sd += __shfl_down_sync(0xffffffffu, sd, o);
    }
    if (lane == 0) {
        g_ssrc[n * H + hh] = ss;
        g_sdst[n * H + hh] = sd;
    }
}

// ---------------- fused softmax + gather aggregation ----------------
template <int H, int C>
__global__ __launch_bounds__(128) void gather_kernel() {
    int d = blockIdx.x;
    int t = threadIdx.x;
    int beg = g_csr_off[d], end = g_csr_off[d + 1];
    const int c0 = t, c1 = t + 128, c2 = t + 256;
    const int h0 = c0 / C, h1 = c1 / C, h2 = c2 / C;
    float sd0 = g_sdst[d * H + h0];
    float sd1 = g_sdst[d * H + h1];
    float sd2 = g_sdst[d * H + h2];
    float n0 = 0.f, n1 = 0.f, n2 = 0.f;
    float e0 = 0.f, e1 = 0.f, e2 = 0.f;
    for (int p = beg; p < end; p++) {
        int s = g_csr_src[p];
        const float* hr = g_h + (size_t)s * DD;
        float t0 = g_ssrc[s * H + h0] + sd0;
        float t1 = g_ssrc[s * H + h1] + sd1;
        float t2 = g_ssrc[s * H + h2] + sd2;
        t0 = t0 > 0.f ? t0 : 0.2f * t0;
        t1 = t1 > 0.f ? t1 : 0.2f * t1;
        t2 = t2 > 0.f ? t2 : 0.2f * t2;
        float w0 = __expf(t0), w1 = __expf(t1), w2 = __expf(t2);
        n0 += w0 * hr[c0];
        n1 += w1 * hr[c1];
        n2 += w2 * hr[c2];
        e0 += w0;
        e1 += w1;
        e2 += w2;
    }
    float* o = g_out + (size_t)d * DD;
    o[c0] = n0 / (e0 + 1e-16f);
    o[c1] = n1 / (e1 + 1e-16f);
    o[c2] = n2 / (e2 + 1e-16f);
}

// ---------------- bias + LayerNorm + ReLU -> g_x ----------------
__global__ void ln_relu_kernel(const float* __restrict__ b, const float* __restrict__ gam,
                               const float* __restrict__ bet) {
    int n = blockIdx.x;
    int t = threadIdx.x;
    float v[3];
    float s = 0.f;
#pragma unroll
    for (int i = 0; i < 3; i++) {
        int c = t + i * 128;
        v[i] = g_out[(size_t)n * DD + c] + b[c];
        s += v[i];
    }
    __shared__ float red[4];
    __shared__ float red2[4];
#pragma unroll
    for (int o = 16; o; o >>= 1) s += __shfl_down_sync(0xffffffffu, s, o);
    if ((t & 31) == 0) red[t >> 5] = s;
    __syncthreads();
    float mu = (red[0] + red[1] + red[2] + red[3]) * (1.f / 384.f);
    float d2 = 0.f;
#pragma unroll
    for (int i = 0; i < 3; i++) {
        float dd = v[i] - mu;
        d2 += dd * dd;
    }
#pragma unroll
    for (int o = 16; o; o >>= 1) d2 += __shfl_down_sync(0xffffffffu, d2, o);
    if ((t & 31) == 0) red2[t >> 5] = d2;
    __syncthreads();
    float var = (red2[0] + red2[1] + red2[2] + red2[3]) * (1.f / 384.f);
    float rstd = rsqrtf(var + 1e-5f);
#pragma unroll
    for (int i = 0; i < 3; i++) {
        int c = t + i * 128;
        float y = (v[i] - mu) * rstd * gam[c] + bet[c];
        g_x[(size_t)n * DD + c] = y > 0.f ? y : 0.f;
    }
}

// ---------------- batch offsets ----------------
__global__ void offsets_kernel(const int* __restrict__ batch) {
    int g = threadIdx.x;
    if (g > BB) return;
    int lo = 0, hi = NN;
    while (lo < hi) {
        int mid = (lo + hi) >> 1;
        if (batch[mid] < g)
            lo = mid + 1;
        else
            hi = mid;
    }
    g_off[g] = lo;
}

// ---------------- residual + relu(bias) + mean pool ----------------
__global__ void pool_kernel(const float* __restrict__ x0, const float* __restrict__ b3,
                            float* __restrict__ out) {
    int g = blockIdx.x, c = threadIdx.x;
    int s = g_off[g], e = g_off[g + 1];
    float bias = b3[c], acc = 0.f;
    for (int n = s; n < e; n++) {
        float v = g_out[(size_t)n * DD + c] + bias;
        acc += x0[(size_t)n * DD + c] + (v > 0.f ? v : 0.f);
    }
    int cnt = e - s;
    out[g * DD + c] = acc / (float)(cnt > 0 ? cnt : 1);
}

// ---------------- host launch ----------------
extern "C" void kernel_launch(void* const* d_in, const int* in_sizes, int n_in,
                              void* d_out, int out_size) {
    const float* x = (const float*)d_in[0];
    const int* ei = (const int*)d_in[1];
    const int* batch = (const int*)d_in[2];
    const float* W1 = (const float*)d_in[3];
    const float* a1s = (const float*)d_in[4];
    const float* a1d = (const float*)d_in[5];
    const float* b1 = (const float*)d_in[6];
    const float* g1 = (const float*)d_in[7];
    const float* be1 = (const float*)d_in[8];
    const float* W2 = (const float*)d_in[9];
    const float* a2s = (const float*)d_in[10];
    const float* a2d = (const float*)d_in[11];
    const float* b2 = (const float*)d_in[12];
    const float* g2 = (const float*)d_in[13];
    const float* be2 = (const float*)d_in[14];
    const float* W3 = (const float*)d_in[15];
    const float* a3s = (const float*)d_in[16];
    const float* a3d = (const float*)d_in[17];
    const float* b3 = (const float*)d_in[18];
    float* out = (float*)d_out;

    void* pv;
    cudaGetSymbolAddress(&pv, g_deg);
    int* degp = (int*)pv;
    cudaGetSymbolAddress(&pv, g_cur);
    int* curp = (int*)pv;
    cudaGetSymbolAddress(&pv, g_x);
    float* xp = (float*)pv;

    cudaFuncSetAttribute(gemm_mma, cudaFuncAttributeMaxDynamicSharedMemorySize, GEMM_SMEM);

    const int* esrc = ei;
    const int* edst = ei + EE;
    int eb = (ETOT + 255) / 256;
    dim3 gemm_grid(6, (NN + 127) / 128);

    // ---- CSR build (reused across layers) ----
    cudaMemsetAsync(degp, 0, NN * sizeof(int));
    count_kernel<<<eb, 256>>>(edst);
    scan_kernel<<<1, 1024>>>();
    cudaMemsetAsync(curp, 0, NN * sizeof(int));
    fill_kernel<<<eb, 256>>>(esrc, edst);

    // ---- layer 1 (H=4, C=96) ----
    gemm_mma<<<gemm_grid, 256, GEMM_SMEM>>>(x, W1);
    s_kernel<4, 96><<<(NN * 4 + 7) / 8, 256>>>(a1s, a1d);
    gather_kernel<4, 96><<<NN, 128>>>();
    ln_relu_kernel<<<NN, 128>>>(b1, g1, be1);

    // ---- layer 2 (H=4, C=96) ----
    gemm_mma<<<gemm_grid, 256, GEMM_SMEM>>>(xp, W2);
    s_kernel<4, 96><<<(NN * 4 + 7) / 8, 256>>>(a2s, a2d);
    gather_kernel<4, 96><<<NN, 128>>>();
    ln_relu_kernel<<<NN, 128>>>(b2, g2, be2);

    // ---- layer 3 (H=6, C=64) ----
    gemm_mma<<<gemm_grid, 256, GEMM_SMEM>>>(xp, W3);
    s_kernel<6, 64><<<(NN * 6 + 7) / 8, 256>>>(a3s, a3d);
    gather_kernel<6, 64><<<NN, 128>>>();

    // ---- pooling ----
    offsets_kernel<<<1, 128>>>(batch);
    pool_kernel<<<BB, DD>>>(x, b3, out);
}

// round 6
// speedup vs baseline: 5.0277x; 1.1717x over previous
#include <cuda_runtime.h>
#include <cstdint>

#define NN 50000
#define EE 500000
#define DD 384
#define BB 64
#define HMAX 6
#define ETOT (EE + NN)

// ---------------- scratch (static device allocations) ----------------
__device__ __align__(16) float g_h[(size_t)NN * DD];    // projected features
__device__ __align__(16) float g_out[(size_t)NN * DD];  // aggregated output
__device__ __align__(16) float g_x[(size_t)NN * DD];    // layer input (x1, x2)
__device__ float g_ssrc[NN * HMAX];
__device__ float g_sdst[NN * HMAX];
__device__ float g_w[(size_t)ETOT * HMAX];  // CSR-ordered normalized alpha
__device__ int g_deg[NN];
__device__ int g_cur[NN];
__device__ int g_csr_off[NN + 1];
__device__ int g_csr_src[ETOT];
__device__ int g_off[BB + 2];

// ================= helpers =================
__device__ __forceinline__ uint32_t smem_u32(const void* p) {
    uint32_t a;
    asm("{ .reg .u64 t; cvta.to.shared.u64 t, %1; cvt.u32.u64 %0, t; }" : "=r"(a) : "l"(p));
    return a;
}
#define CP16(sa, g) asm volatile("cp.async.cg.shared.global [%0], [%1], 16;" ::"r"(sa), "l"(g))
#define CP_COMMIT() asm volatile("cp.async.commit_group;" ::: "memory")

__device__ __forceinline__ uint32_t to_tf32(float x) {
    uint32_t u;
    asm("cvt.rna.tf32.f32 %0, %1;" : "=r"(u) : "f"(x));
    return u;
}
__device__ __forceinline__ void mma_tf32(float* d, uint32_t a0, uint32_t a1, uint32_t a2,
                                         uint32_t a3, uint32_t b0, uint32_t b1) {
    asm volatile(
        "mma.sync.aligned.m16n8k8.row.col.f32.tf32.tf32.f32 "
        "{%0,%1,%2,%3}, {%4,%5,%6,%7}, {%8,%9}, {%0,%1,%2,%3};"
        : "+f"(d[0]), "+f"(d[1]), "+f"(d[2]), "+f"(d[3])
        : "r"(a0), "r"(a1), "r"(a2), "r"(a3), "r"(b0), "r"(b1));
}

// ================= tf32 mma.sync GEMM v3: g_h[M,384] = A[M,384] @ W[384,384] =================
// grid (3, 391), 256 threads. CTA tile 128(M) x 128(N), warp tile 32x64.
// smem per stage: As[128][36] + Bs[32][136] floats.
#define ST_FLOATS (4608 + 4352)
#define GEMM_SMEM (2 * ST_FLOATS * 4)

__global__ __launch_bounds__(256) void gemm_mma(const float* __restrict__ A,
                                                const float* __restrict__ W) {
    extern __shared__ float sm[];
    int tid = threadIdx.x;
    int m0 = blockIdx.y * 128, n0 = blockIdx.x * 128;
    int lane = tid & 31, wid = tid >> 5;
    int wm = wid & 3, wn = wid >> 2;   // 4(M) x 2(N) warps, warp tile 32x64
    int r = lane >> 2, kq = lane & 3;  // groupID, threadID_in_group

    float acc[2][8][4];
#pragma unroll
    for (int i = 0; i < 2; i++)
#pragma unroll
        for (int j = 0; j < 8; j++)
#pragma unroll
            for (int q = 0; q < 4; q++) acc[i][j][q] = 0.f;

    auto issue = [&](int c, int st) {
        float* As = sm + st * ST_FLOATS;
        float* Bs = As + 4608;
        int k0 = c * 32;
#pragma unroll
        for (int i = 0; i < 4; i++) {
            int idx = i * 256 + tid;
            int m = idx >> 3, seg = idx & 7;
            int row = m0 + m;
            if (row > NN - 1) row = NN - 1;
            CP16(smem_u32(As + m * 36 + seg * 4), A + (size_t)row * DD + k0 + seg * 4);
        }
#pragma unroll
        for (int i = 0; i < 4; i++) {
            int idx = i * 256 + tid;
            int kr = idx >> 5, seg = idx & 31;
            CP16(smem_u32(Bs + kr * 136 + seg * 4), W + (size_t)(k0 + kr) * DD + n0 + seg * 4);
        }
        CP_COMMIT();
    };

    issue(0, 0);
    for (int c = 0; c < 12; c++) {
        int st = c & 1;
        if (c < 11) {
            issue(c + 1, st ^ 1);
            asm volatile("cp.async.wait_group 1;" ::: "memory");
        } else {
            asm volatile("cp.async.wait_group 0;" ::: "memory");
        }
        __syncthreads();
        const float* As = sm + st * ST_FLOATS;
        const float* Bs = As + 4608;
#pragma unroll
        for (int ks = 0; ks < 4; ks++) {
            int kk = ks * 8;
            uint32_t a[2][4], b[8][2];
#pragma unroll
            for (int mi = 0; mi < 2; mi++) {
                int row = wm * 32 + mi * 16 + r;
                a[mi][0] = to_tf32(As[row * 36 + kk + kq]);
                a[mi][1] = to_tf32(As[(row + 8) * 36 + kk + kq]);
                a[mi][2] = to_tf32(As[row * 36 + kk + kq + 4]);
                a[mi][3] = to_tf32(As[(row + 8) * 36 + kk + kq + 4]);
            }
#pragma unroll
            for (int j = 0; j < 8; j++) {
                int col = wn * 64 + j * 8 + r;
                b[j][0] = to_tf32(Bs[(kk + kq) * 136 + col]);
                b[j][1] = to_tf32(Bs[(kk + kq + 4) * 136 + col]);
            }
#pragma unroll
            for (int mi = 0; mi < 2; mi++)
#pragma unroll
                for (int j = 0; j < 8; j++)
                    mma_tf32(acc[mi][j], a[mi][0], a[mi][1], a[mi][2], a[mi][3], b[j][0], b[j][1]);
        }
        __syncthreads();
    }

#pragma unroll
    for (int mi = 0; mi < 2; mi++) {
#pragma unroll
        for (int j = 0; j < 8; j++) {
            int row = m0 + wm * 32 + mi * 16 + r;
            int col = n0 + wn * 64 + j * 8 + kq * 2;
            if (row < NN)
                *(float2*)&g_h[(size_t)row * DD + col] = make_float2(acc[mi][j][0], acc[mi][j][1]);
            if (row + 8 < NN)
                *(float2*)&g_h[(size_t)(row + 8) * DD + col] =
                    make_float2(acc[mi][j][2], acc[mi][j][3]);
        }
    }
}

// ---------------- CSR build ----------------
__global__ void count_kernel(const int* __restrict__ edst) {
    int e = blockIdx.x * blockDim.x + threadIdx.x;
    if (e >= ETOT) return;
    int d = (e < EE) ? edst[e] : (e - EE);
    atomicAdd(&g_deg[d], 1);
}

__global__ void scan_kernel() {
    const int T = 1024;
    const int CH = (NN + T - 1) / T;
    __shared__ int warp_sums[32];
    int t = threadIdx.x;
    int base = t * CH;
    int s = 0;
    for (int i = 0; i < CH; i++) {
        int idx = base + i;
        if (idx < NN) s += g_deg[idx];
    }
    int lane = t & 31, wid = t >> 5;
    int v = s;
#pragma unroll
    for (int o = 1; o < 32; o <<= 1) {
        int u = __shfl_up_sync(0xffffffffu, v, o);
        if (lane >= o) v += u;
    }
    if (lane == 31) warp_sums[wid] = v;
    __syncthreads();
    if (wid == 0) {
        int w = warp_sums[lane];
#pragma unroll
        for (int o = 1; o < 32; o <<= 1) {
            int u = __shfl_up_sync(0xffffffffu, w, o);
            if (lane >= o) w += u;
        }
        warp_sums[lane] = w;
    }
    __syncthreads();
    int excl = v - s + (wid > 0 ? warp_sums[wid - 1] : 0);
    int run = excl;
    for (int i = 0; i < CH; i++) {
        int idx = base + i;
        if (idx < NN) {
            g_csr_off[idx] = run;
            run += g_deg[idx];
        }
    }
    if (t == 0) g_csr_off[NN] = ETOT;
}

__global__ void fill_kernel(const int* __restrict__ esrc, const int* __restrict__ edst) {
    int e = blockIdx.x * blockDim.x + threadIdx.x;
    if (e >= ETOT) return;
    int s, d;
    if (e < EE) {
        s = esrc[e];
        d = edst[e];
    } else {
        s = d = e - EE;
    }
    int slot = g_csr_off[d] + atomicAdd(&g_cur[d], 1);
    g_csr_src[slot] = s;
}

// ---------------- attention logits ----------------
template <int H, int C>
__global__ void s_kernel(const float* __restrict__ a_src, const float* __restrict__ a_dst) {
    int gw = (blockIdx.x * blockDim.x + threadIdx.x) >> 5;
    int lane = threadIdx.x & 31;
    int n = gw / H, hh = gw % H;
    if (n >= NN) return;
    float ss = 0.f, sd = 0.f;
    for (int c = lane; c < C; c += 32) {
        float v = g_h[(size_t)n * DD + hh * C + c];
        ss += v * a_src[hh * C + c];
        sd += v * a_dst[hh * C + c];
    }
#pragma unroll
    for (int o = 16; o; o >>= 1) {
        ss += __shfl_down_sync(0xffffffffu, ss, o);
        sd += __shfl_down_sync(0xffffffffu, sd, o);
    }
    if (lane == 0) {
        g_ssrc[n * H + hh] = ss;
        g_sdst[n * H + hh] = sd;
    }
}

// ---------------- per-edge normalized alpha (warp per dst) ----------------
// g_w[p*H+h] = exp(lrelu(ssrc[s]+sdst[d])) / (sum_p' exp + 1e-16), CSR order
template <int H>
__global__ __launch_bounds__(256) void alpha_kernel() {
    const int PI = 32 / H;  // edges handled per warp pass
    int gw = (blockIdx.x * blockDim.x + threadIdx.x) >> 5;
    int lane = threadIdx.x & 31;
    if (gw >= NN) return;
    int d = gw;
    int beg = g_csr_off[d], end = g_csr_off[d + 1];
    int pi = lane / H, hh = lane - pi * H;
    bool act = pi < PI;
    float sd = act ? g_sdst[d * H + hh] : 0.f;
    float dsum = 0.f;
    for (int p0 = beg; p0 < end; p0 += PI) {
        int p = p0 + pi;
        float w = 0.f;
        if (act && p < end) {
            int s = g_csr_src[p];
            float t = g_ssrc[s * H + hh] + sd;
            t = t > 0.f ? t : 0.2f * t;
            w = __expf(t);
            g_w[(size_t)p * H + hh] = w;
        }
        dsum += w;
    }
    // sum over pi-groups for this lane's h: lanes {h, h+H, h+2H, ...}
    float denom = 0.f;
#pragma unroll
    for (int k = 0; k < PI; k++) denom += __shfl_sync(0xffffffffu, dsum, hh + k * H);
    float inv = 1.f / (denom + 1e-16f);
    for (int p0 = beg; p0 < end; p0 += PI) {
        int p = p0 + pi;
        if (act && p < end) g_w[(size_t)p * H + hh] *= inv;
    }
}

// ---------------- gather aggregation: pure alpha-weighted row sum ----------------
template <int H, int C>
__global__ __launch_bounds__(128) void gather_kernel() {
    int d = blockIdx.x;
    int t = threadIdx.x;
    int lane = t & 31;
    int beg = g_csr_off[d], end = g_csr_off[d + 1];
    const int c0 = t, c1 = t + 128, c2 = t + 256;
    const int h0 = c0 / C, h1 = c1 / C, h2 = c2 / C;
    float n0 = 0.f, n1 = 0.f, n2 = 0.f;
    for (int p = beg; p < end; p++) {
        int s = g_csr_src[p];
        float av = (lane < H) ? g_w[(size_t)p * H + lane] : 0.f;
        float a0 = __shfl_sync(0xffffffffu, av, h0);
        float a1 = __shfl_sync(0xffffffffu, av, h1);
        float a2 = __shfl_sync(0xffffffffu, av, h2);
        const float* hr = g_h + (size_t)s * DD;
        n0 += a0 * hr[c0];
        n1 += a1 * hr[c1];
        n2 += a2 * hr[c2];
    }
    float* o = g_out + (size_t)d * DD;
    o[c0] = n0;
    o[c1] = n1;
    o[c2] = n2;
}

// ---------------- bias + LayerNorm + ReLU -> g_x ----------------
__global__ void ln_relu_kernel(const float* __restrict__ b, const float* __restrict__ gam,
                               const float* __restrict__ bet) {
    int n = blockIdx.x;
    int t = threadIdx.x;
    float v[3];
    float s = 0.f;
#pragma unroll
    for (int i = 0; i < 3; i++) {
        int c = t + i * 128;
        v[i] = g_out[(size_t)n * DD + c] + b[c];
        s += v[i];
    }
    __shared__ float red[4];
    __shared__ float red2[4];
#pragma unroll
    for (int o = 16; o; o >>= 1) s += __shfl_down_sync(0xffffffffu, s, o);
    if ((t & 31) == 0) red[t >> 5] = s;
    __syncthreads();
    float mu = (red[0] + red[1] + red[2] + red[3]) * (1.f / 384.f);
    float d2 = 0.f;
#pragma unroll
    for (int i = 0; i < 3; i++) {
        float dd = v[i] - mu;
        d2 += dd * dd;
    }
#pragma unroll
    for (int o = 16; o; o >>= 1) d2 += __shfl_down_sync(0xffffffffu, d2, o);
    if ((t & 31) == 0) red2[t >> 5] = d2;
    __syncthreads();
    float var = (red2[0] + red2[1] + red2[2] + red2[3]) * (1.f / 384.f);
    float rstd = rsqrtf(var + 1e-5f);
#pragma unroll
    for (int i = 0; i < 3; i++) {
        int c = t + i * 128;
        float y = (v[i] - mu) * rstd * gam[c] + bet[c];
        g_x[(size_t)n * DD + c] = y > 0.f ? y : 0.f;
    }
}

// ---------------- batch offsets ----------------
__global__ void offsets_kernel(const int* __restrict__ batch) {
    int g = threadIdx.x;
    if (g > BB) return;
    int lo = 0, hi = NN;
    while (lo < hi) {
        int mid = (lo + hi) >> 1;
        if (batch[mid] < g)
            lo = mid + 1;
        else
            hi = mid;
    }
    g_off[g] = lo;
}

// ---------------- residual + relu(bias) + mean pool ----------------
__global__ void pool_kernel(const float* __restrict__ x0, const float* __restrict__ b3,
                            float* __restrict__ out) {
    int g = blockIdx.x, c = threadIdx.x;
    int s = g_off[g], e = g_off[g + 1];
    float bias = b3[c], acc = 0.f;
    for (int n = s; n < e; n++) {
        float v = g_out[(size_t)n * DD + c] + bias;
        acc += x0[(size_t)n * DD + c] + (v > 0.f ? v : 0.f);
    }
    int cnt = e - s;
    out[g * DD + c] = acc / (float)(cnt > 0 ? cnt : 1);
}

// ---------------- host launch ----------------
extern "C" void kernel_launch(void* const* d_in, const int* in_sizes, int n_in,
                              void* d_out, int out_size) {
    const float* x = (const float*)d_in[0];
    const int* ei = (const int*)d_in[1];
    const int* batch = (const int*)d_in[2];
    const float* W1 = (const float*)d_in[3];
    const float* a1s = (const float*)d_in[4];
    const float* a1d = (const float*)d_in[5];
    const float* b1 = (const float*)d_in[6];
    const float* g1 = (const float*)d_in[7];
    const float* be1 = (const float*)d_in[8];
    const float* W2 = (const float*)d_in[9];
    const float* a2s = (const float*)d_in[10];
    const float* a2d = (const float*)d_in[11];
    const float* b2 = (const float*)d_in[12];
    const float* g2 = (const float*)d_in[13];
    const float* be2 = (const float*)d_in[14];
    const float* W3 = (const float*)d_in[15];
    const float* a3s = (const float*)d_in[16];
    const float* a3d = (const float*)d_in[17];
    const float* b3 = (const float*)d_in[18];
    float* out = (float*)d_out;

    void* pv;
    cudaGetSymbolAddress(&pv, g_deg);
    int* degp = (int*)pv;
    cudaGetSymbolAddress(&pv, g_cur);
    int* curp = (int*)pv;
    cudaGetSymbolAddress(&pv, g_x);
    float* xp = (float*)pv;

    cudaFuncSetAttribute(gemm_mma, cudaFuncAttributeMaxDynamicSharedMemorySize, GEMM_SMEM);

    const int* esrc = ei;
    const int* edst = ei + EE;
    int eb = (ETOT + 255) / 256;
    dim3 gemm_grid(3, (NN + 127) / 128);
    int ab = (NN * 32 + 255) / 256;  // warp-per-dst blocks

    // ---- CSR build (reused across layers) ----
    cudaMemsetAsync(degp, 0, NN * sizeof(int));
    count_kernel<<<eb, 256>>>(edst);
    scan_kernel<<<1, 1024>>>();
    cudaMemsetAsync(curp, 0, NN * sizeof(int));
    fill_kernel<<<eb, 256>>>(esrc, edst);

    // ---- layer 1 (H=4, C=96) ----
    gemm_mma<<<gemm_grid, 256, GEMM_SMEM>>>(x, W1);
    s_kernel<4, 96><<<(NN * 4 + 7) / 8, 256>>>(a1s, a1d);
    alpha_kernel<4><<<ab, 256>>>();
    gather_kernel<4, 96><<<NN, 128>>>();
    ln_relu_kernel<<<NN, 128>>>(b1, g1, be1);

    // ---- layer 2 (H=4, C=96) ----
    gemm_mma<<<gemm_grid, 256, GEMM_SMEM>>>(xp, W2);
    s_kernel<4, 96><<<(NN * 4 + 7) / 8, 256>>>(a2s, a2d);
    alpha_kernel<4><<<ab, 256>>>();
    gather_kernel<4, 96><<<NN, 128>>>();
    ln_relu_kernel<<<NN, 128>>>(b2, g2, be2);

    // ---- layer 3 (H=6, C=64) ----
    gemm_mma<<<gemm_grid, 256, GEMM_SMEM>>>(xp, W3);
    s_kernel<6, 64><<<(NN * 6 + 7) / 8, 256>>>(a3s, a3d);
    alpha_kernel<6><<<ab, 256>>>();
    gather_kernel<6, 64><<<NN, 128>>>();

    // ---- pooling ----
    offsets_kernel<<<1, 128>>>(batch);
    pool_kernel<<<BB, DD>>>(x, b3, out);
}

// round 7
// speedup vs baseline: 5.9897x; 1.1913x over previous
#include <cuda_runtime.h>
#include <cstdint>

#define NN 50000
#define EE 500000
#define DD 384
#define BB 64
#define HMAX 6
#define ETOT (EE + NN)
#define MAXDEG 512

// ---------------- scratch (static device allocations) ----------------
__device__ __align__(16) float g_h[(size_t)NN * DD];    // projected features
__device__ __align__(16) float g_out[(size_t)NN * DD];  // layer-3 aggregated output
__device__ __align__(16) float g_x[(size_t)NN * DD];    // layer input (x1, x2)
__device__ float g_ssrc[NN * HMAX];
__device__ float g_sdst[NN * HMAX];
__device__ int g_deg[NN];
__device__ int g_cur[NN];
__device__ int g_csr_off[NN + 1];
__device__ int g_csr_src[ETOT];
__device__ int g_off[BB + 2];

// ================= helpers =================
__device__ __forceinline__ uint32_t smem_u32(const void* p) {
    uint32_t a;
    asm("{ .reg .u64 t; cvta.to.shared.u64 t, %1; cvt.u32.u64 %0, t; }" : "=r"(a) : "l"(p));
    return a;
}
#define CP16(sa, g) asm volatile("cp.async.cg.shared.global [%0], [%1], 16;" ::"r"(sa), "l"(g))
#define CP_COMMIT() asm volatile("cp.async.commit_group;" ::: "memory")

__device__ __forceinline__ uint32_t to_tf32(float x) {
    uint32_t u;
    asm("cvt.rna.tf32.f32 %0, %1;" : "=r"(u) : "f"(x));
    return u;
}
__device__ __forceinline__ void mma_tf32(float* d, uint32_t a0, uint32_t a1, uint32_t a2,
                                         uint32_t a3, uint32_t b0, uint32_t b1) {
    asm volatile(
        "mma.sync.aligned.m16n8k8.row.col.f32.tf32.tf32.f32 "
        "{%0,%1,%2,%3}, {%4,%5,%6,%7}, {%8,%9}, {%0,%1,%2,%3};"
        : "+f"(d[0]), "+f"(d[1]), "+f"(d[2]), "+f"(d[3])
        : "r"(a0), "r"(a1), "r"(a2), "r"(a3), "r"(b0), "r"(b1));
}

// ================= tf32 mma.sync GEMM: g_h[M,384] = A[M,384] @ W[384,384] =================
#define ST_FLOATS (4608 + 4352)
#define GEMM_SMEM (2 * ST_FLOATS * 4)

__global__ __launch_bounds__(256) void gemm_mma(const float* __restrict__ A,
                                                const float* __restrict__ W) {
    extern __shared__ float sm[];
    int tid = threadIdx.x;
    int m0 = blockIdx.y * 128, n0 = blockIdx.x * 128;
    int lane = tid & 31, wid = tid >> 5;
    int wm = wid & 3, wn = wid >> 2;
    int r = lane >> 2, kq = lane & 3;

    float acc[2][8][4];
#pragma unroll
    for (int i = 0; i < 2; i++)
#pragma unroll
        for (int j = 0; j < 8; j++)
#pragma unroll
            for (int q = 0; q < 4; q++) acc[i][j][q] = 0.f;

    auto issue = [&](int c, int st) {
        float* As = sm + st * ST_FLOATS;
        float* Bs = As + 4608;
        int k0 = c * 32;
#pragma unroll
        for (int i = 0; i < 4; i++) {
            int idx = i * 256 + tid;
            int m = idx >> 3, seg = idx & 7;
            int row = m0 + m;
            if (row > NN - 1) row = NN - 1;
            CP16(smem_u32(As + m * 36 + seg * 4), A + (size_t)row * DD + k0 + seg * 4);
        }
#pragma unroll
        for (int i = 0; i < 4; i++) {
            int idx = i * 256 + tid;
            int kr = idx >> 5, seg = idx & 31;
            CP16(smem_u32(Bs + kr * 136 + seg * 4), W + (size_t)(k0 + kr) * DD + n0 + seg * 4);
        }
        CP_COMMIT();
    };

    issue(0, 0);
    for (int c = 0; c < 12; c++) {
        int st = c & 1;
        if (c < 11) {
            issue(c + 1, st ^ 1);
            asm volatile("cp.async.wait_group 1;" ::: "memory");
        } else {
            asm volatile("cp.async.wait_group 0;" ::: "memory");
        }
        __syncthreads();
        const float* As = sm + st * ST_FLOATS;
        const float* Bs = As + 4608;
#pragma unroll
        for (int ks = 0; ks < 4; ks++) {
            int kk = ks * 8;
            uint32_t a[2][4], b[8][2];
#pragma unroll
            for (int mi = 0; mi < 2; mi++) {
                int row = wm * 32 + mi * 16 + r;
                a[mi][0] = to_tf32(As[row * 36 + kk + kq]);
                a[mi][1] = to_tf32(As[(row + 8) * 36 + kk + kq]);
                a[mi][2] = to_tf32(As[row * 36 + kk + kq + 4]);
                a[mi][3] = to_tf32(As[(row + 8) * 36 + kk + kq + 4]);
            }
#pragma unroll
            for (int j = 0; j < 8; j++) {
                int col = wn * 64 + j * 8 + r;
                b[j][0] = to_tf32(Bs[(kk + kq) * 136 + col]);
                b[j][1] = to_tf32(Bs[(kk + kq + 4) * 136 + col]);
            }
#pragma unroll
            for (int mi = 0; mi < 2; mi++)
#pragma unroll
                for (int j = 0; j < 8; j++)
                    mma_tf32(acc[mi][j], a[mi][0], a[mi][1], a[mi][2], a[mi][3], b[j][0], b[j][1]);
        }
        __syncthreads();
    }

#pragma unroll
    for (int mi = 0; mi < 2; mi++) {
#pragma unroll
        for (int j = 0; j < 8; j++) {
            int row = m0 + wm * 32 + mi * 16 + r;
            int col = n0 + wn * 64 + j * 8 + kq * 2;
            if (row < NN)
                *(float2*)&g_h[(size_t)row * DD + col] = make_float2(acc[mi][j][0], acc[mi][j][1]);
            if (row + 8 < NN)
                *(float2*)&g_h[(size_t)(row + 8) * DD + col] =
                    make_float2(acc[mi][j][2], acc[mi][j][3]);
        }
    }
}

// ---------------- CSR build ----------------
__global__ void count_kernel(const int* __restrict__ edst) {
    int e = blockIdx.x * blockDim.x + threadIdx.x;
    if (e >= ETOT) return;
    int d = (e < EE) ? edst[e] : (e - EE);
    atomicAdd(&g_deg[d], 1);
}

__global__ void scan_kernel() {
    const int T = 1024;
    const int CH = (NN + T - 1) / T;
    __shared__ int warp_sums[32];
    int t = threadIdx.x;
    int base = t * CH;
    int s = 0;
    for (int i = 0; i < CH; i++) {
        int idx = base + i;
        if (idx < NN) s += g_deg[idx];
    }
    int lane = t & 31, wid = t >> 5;
    int v = s;
#pragma unroll
    for (int o = 1; o < 32; o <<= 1) {
        int u = __shfl_up_sync(0xffffffffu, v, o);
        if (lane >= o) v += u;
    }
    if (lane == 31) warp_sums[wid] = v;
    __syncthreads();
    if (wid == 0) {
        int w = warp_sums[lane];
#pragma unroll
        for (int o = 1; o < 32; o <<= 1) {
            int u = __shfl_up_sync(0xffffffffu, w, o);
            if (lane >= o) w += u;
        }
        warp_sums[lane] = w;
    }
    __syncthreads();
    int excl = v - s + (wid > 0 ? warp_sums[wid - 1] : 0);
    int run = excl;
    for (int i = 0; i < CH; i++) {
        int idx = base + i;
        if (idx < NN) {
            g_csr_off[idx] = run;
            run += g_deg[idx];
        }
    }
    if (t == 0) g_csr_off[NN] = ETOT;
}

__global__ void fill_kernel(const int* __restrict__ esrc, const int* __restrict__ edst) {
    int e = blockIdx.x * blockDim.x + threadIdx.x;
    if (e >= ETOT) return;
    int s, d;
    if (e < EE) {
        s = esrc[e];
        d = edst[e];
    } else {
        s = d = e - EE;
    }
    int slot = g_csr_off[d] + atomicAdd(&g_cur[d], 1);
    g_csr_src[slot] = s;
}

// ---------------- attention logits ----------------
template <int H, int C>
__global__ void s_kernel(const float* __restrict__ a_src, const float* __restrict__ a_dst) {
    int gw = (blockIdx.x * blockDim.x + threadIdx.x) >> 5;
    int lane = threadIdx.x & 31;
    int n = gw / H, hh = gw % H;
    if (n >= NN) return;
    float ss = 0.f, sd = 0.f;
    for (int c = lane; c < C; c += 32) {
        float v = g_h[(size_t)n * DD + hh * C + c];
        ss += v * a_src[hh * C + c];
        sd += v * a_dst[hh * C + c];
    }
#pragma unroll
    for (int o = 16; o; o >>= 1) {
        ss += __shfl_down_sync(0xffffffffu, ss, o);
        sd += __shfl_down_sync(0xffffffffu, sd, o);
    }
    if (lane == 0) {
        g_ssrc[n * H + hh] = ss;
        g_sdst[n * H + hh] = sd;
    }
}

// ---------------- fused softmax-alpha + gather + (bias+LN+ReLU) ----------------
// One block per dst node (128 threads). If DO_LN: writes relu(LN(agg+b)) to g_x,
// else writes raw agg to g_out.
template <int H, int C, bool DO_LN>
__global__ __launch_bounds__(128) void agg_kernel(const float* __restrict__ b,
                                                  const float* __restrict__ gam,
                                                  const float* __restrict__ bet) {
    __shared__ float wbuf[MAXDEG * H];
    __shared__ float invd[H];
    __shared__ float red[4], red2[4];
    int d = blockIdx.x;
    int t = threadIdx.x;
    int beg = g_csr_off[d], end = g_csr_off[d + 1];
    int deg = end - beg;
    const int c0 = t, c1 = t + 128, c2 = t + 256;
    const int h0 = c0 / C, h1 = c1 / C, h2 = c2 / C;
    float n0 = 0.f, n1 = 0.f, n2 = 0.f;

    if (deg <= MAXDEG) {
        int items = deg * H;
        for (int i = t; i < items; i += 128) {
            int p = i / H, h = i - p * H;
            int s = g_csr_src[beg + p];
            float tt = g_ssrc[s * H + h] + g_sdst[d * H + h];
            tt = tt > 0.f ? tt : 0.2f * tt;
            wbuf[i] = __expf(tt);
        }
        __syncthreads();
        if (t < H) {
            float dn = 0.f;
            for (int p = 0; p < deg; p++) dn += wbuf[p * H + t];
            invd[t] = 1.f / (dn + 1e-16f);
        }
        __syncthreads();
        for (int i = t; i < items; i += 128) {
            int h = i - (i / H) * H;
            wbuf[i] *= invd[h];
        }
        __syncthreads();
        int p = 0;
        for (; p + 2 <= deg; p += 2) {
            int s0 = g_csr_src[beg + p], s1 = g_csr_src[beg + p + 1];
            float a0 = wbuf[p * H + h0], a1 = wbuf[p * H + h1], a2 = wbuf[p * H + h2];
            float q0 = wbuf[(p + 1) * H + h0], q1 = wbuf[(p + 1) * H + h1],
                  q2 = wbuf[(p + 1) * H + h2];
            const float* r0 = g_h + (size_t)s0 * DD;
            const float* r1 = g_h + (size_t)s1 * DD;
            n0 += a0 * r0[c0] + q0 * r1[c0];
            n1 += a1 * r0[c1] + q1 * r1[c1];
            n2 += a2 * r0[c2] + q2 * r1[c2];
        }
        if (p < deg) {
            int s0 = g_csr_src[beg + p];
            const float* r0 = g_h + (size_t)s0 * DD;
            n0 += wbuf[p * H + h0] * r0[c0];
            n1 += wbuf[p * H + h1] * r0[c1];
            n2 += wbuf[p * H + h2] * r0[c2];
        }
    } else {
        // fallback: per-thread recompute (never expected on this dataset)
        float sd0 = g_sdst[d * H + h0], sd1 = g_sdst[d * H + h1], sd2 = g_sdst[d * H + h2];
        float e0 = 0.f, e1 = 0.f, e2 = 0.f;
        for (int p = beg; p < end; p++) {
            int s = g_csr_src[p];
            const float* hr = g_h + (size_t)s * DD;
            float t0 = g_ssrc[s * H + h0] + sd0;
            float t1 = g_ssrc[s * H + h1] + sd1;
            float t2 = g_ssrc[s * H + h2] + sd2;
            t0 = t0 > 0.f ? t0 : 0.2f * t0;
            t1 = t1 > 0.f ? t1 : 0.2f * t1;
            t2 = t2 > 0.f ? t2 : 0.2f * t2;
            float w0 = __expf(t0), w1 = __expf(t1), w2 = __expf(t2);
            n0 += w0 * hr[c0];
            n1 += w1 * hr[c1];
            n2 += w2 * hr[c2];
            e0 += w0;
            e1 += w1;
            e2 += w2;
        }
        n0 /= (e0 + 1e-16f);
        n1 /= (e1 + 1e-16f);
        n2 /= (e2 + 1e-16f);
    }

    if (DO_LN) {
        float v0 = n0 + b[c0], v1 = n1 + b[c1], v2 = n2 + b[c2];
        float s = v0 + v1 + v2;
#pragma unroll
        for (int o = 16; o; o >>= 1) s += __shfl_down_sync(0xffffffffu, s, o);
        if ((t & 31) == 0) red[t >> 5] = s;
        __syncthreads();
        float mu = (red[0] + red[1] + red[2] + red[3]) * (1.f / 384.f);
        float dv0 = v0 - mu, dv1 = v1 - mu, dv2 = v2 - mu;
        float d2 = dv0 * dv0 + dv1 * dv1 + dv2 * dv2;
#pragma unroll
        for (int o = 16; o; o >>= 1) d2 += __shfl_down_sync(0xffffffffu, d2, o);
        if ((t & 31) == 0) red2[t >> 5] = d2;
        __syncthreads();
        float var = (red2[0] + red2[1] + red2[2] + red2[3]) * (1.f / 384.f);
        float rstd = rsqrtf(var + 1e-5f);
        float y0 = dv0 * rstd * gam[c0] + bet[c0];
        float y1 = dv1 * rstd * gam[c1] + bet[c1];
        float y2 = dv2 * rstd * gam[c2] + bet[c2];
        float* o = g_x + (size_t)d * DD;
        o[c0] = y0 > 0.f ? y0 : 0.f;
        o[c1] = y1 > 0.f ? y1 : 0.f;
        o[c2] = y2 > 0.f ? y2 : 0.f;
    } else {
        float* o = g_out + (size_t)d * DD;
        o[c0] = n0;
        o[c1] = n1;
        o[c2] = n2;
    }
}

// ---------------- batch offsets ----------------
__global__ void offsets_kernel(const int* __restrict__ batch) {
    int g = threadIdx.x;
    if (g > BB) return;
    int lo = 0, hi = NN;
    while (lo < hi) {
        int mid = (lo + hi) >> 1;
        if (batch[mid] < g)
            lo = mid + 1;
        else
            hi = mid;
    }
    g_off[g] = lo;
}

// ---------------- residual + relu(bias) + mean pool (sliced, atomic finish) ----------------
__global__ void pool_kernel(const float* __restrict__ x0, const float* __restrict__ b3,
                            float* __restrict__ out) {
    int g = blockIdx.x, slice = blockIdx.y, c = threadIdx.x;
    int s = g_off[g], e = g_off[g + 1];
    float bias = b3[c], acc = 0.f;
    for (int n = s + slice; n < e; n += 8) {
        float v = g_out[(size_t)n * DD + c] + bias;
        acc += x0[(size_t)n * DD + c] + (v > 0.f ? v : 0.f);
    }
    int cnt = e - s;
    if (cnt < 1) cnt = 1;
    atomicAdd(&out[g * DD + c], acc / (float)cnt);
}

// ---------------- host launch ----------------
extern "C" void kernel_launch(void* const* d_in, const int* in_sizes, int n_in,
                              void* d_out, int out_size) {
    const float* x = (const float*)d_in[0];
    const int* ei = (const int*)d_in[1];
    const int* batch = (const int*)d_in[2];
    const float* W1 = (const float*)d_in[3];
    const float* a1s = (const float*)d_in[4];
    const float* a1d = (const float*)d_in[5];
    const float* b1 = (const float*)d_in[6];
    const float* g1 = (const float*)d_in[7];
    const float* be1 = (const float*)d_in[8];
    const float* W2 = (const float*)d_in[9];
    const float* a2s = (const float*)d_in[10];
    const float* a2d = (const float*)d_in[11];
    const float* b2 = (const float*)d_in[12];
    const float* g2 = (const float*)d_in[13];
    const float* be2 = (const float*)d_in[14];
    const float* W3 = (const float*)d_in[15];
    const float* a3s = (const float*)d_in[16];
    const float* a3d = (const float*)d_in[17];
    const float* b3 = (const float*)d_in[18];
    float* out = (float*)d_out;

    static cudaStream_t aux = nullptr;
    static cudaEvent_t ev0 = nullptr, ev1 = nullptr;
    if (aux == nullptr) {
        cudaStreamCreateWithFlags(&aux, cudaStreamNonBlocking);
        cudaEventCreateWithFlags(&ev0, cudaEventDisableTiming);
        cudaEventCreateWithFlags(&ev1, cudaEventDisableTiming);
    }

    void* pv;
    cudaGetSymbolAddress(&pv, g_deg);
    int* degp = (int*)pv;
    cudaGetSymbolAddress(&pv, g_cur);
    int* curp = (int*)pv;
    cudaGetSymbolAddress(&pv, g_x);
    float* xp = (float*)pv;

    cudaFuncSetAttribute(gemm_mma, cudaFuncAttributeMaxDynamicSharedMemorySize, GEMM_SMEM);

    const int* esrc = ei;
    const int* edst = ei + EE;
    int eb = (ETOT + 255) / 256;
    dim3 gemm_grid(3, (NN + 127) / 128);

    // ---- fork: CSR build + offsets + output zeroing on aux stream ----
    cudaEventRecord(ev0, 0);
    cudaStreamWaitEvent(aux, ev0, 0);
    cudaMemsetAsync(degp, 0, NN * sizeof(int), aux);
    count_kernel<<<eb, 256, 0, aux>>>(edst);
    scan_kernel<<<1, 1024, 0, aux>>>();
    cudaMemsetAsync(curp, 0, NN * sizeof(int), aux);
    fill_kernel<<<eb, 256, 0, aux>>>(esrc, edst);
    offsets_kernel<<<1, 128, 0, aux>>>(batch);
    cudaMemsetAsync(out, 0, (size_t)BB * DD * sizeof(float), aux);
    cudaEventRecord(ev1, aux);

    // ---- layer 1 (H=4, C=96) ----
    gemm_mma<<<gemm_grid, 256, GEMM_SMEM>>>(x, W1);
    s_kernel<4, 96><<<(NN * 4 + 7) / 8, 256>>>(a1s, a1d);
    cudaStreamWaitEvent(0, ev1, 0);  // join CSR before aggregation
    agg_kernel<4, 96, true><<<NN, 128>>>(b1, g1, be1);

    // ---- layer 2 (H=4, C=96) ----
    gemm_mma<<<gemm_grid, 256, GEMM_SMEM>>>(xp, W2);
    s_kernel<4, 96><<<(NN * 4 + 7) / 8, 256>>>(a2s, a2d);
    agg_kernel<4, 96, true><<<NN, 128>>>(b2, g2, be2);

    // ---- layer 3 (H=6, C=64) ----
    gemm_mma<<<gemm_grid, 256, GEMM_SMEM>>>(xp, W3);
    s_kernel<6, 64><<<(NN * 6 + 7) / 8, 256>>>(a3s, a3d);
    agg_kernel<6, 64, false><<<NN, 128>>>(nullptr, nullptr, nullptr);

    // ---- pooling ----
    pool_kernel<<<dim3(BB, 8), DD>>>(x, b3, out);
}

// round 8
// speedup vs baseline: 6.4296x; 1.0734x over previous
#include <cuda_runtime.h>
#include <cstdint>

#define NN 50000
#define EE 500000
#define DD 384
#define BB 64
#define HMAX 6
#define ETOT (EE + NN)
#define MAXDEG 512

// ---------------- scratch (static device allocations) ----------------
__device__ __align__(16) float g_h[(size_t)NN * DD];    // projected features
__device__ __align__(16) float g_out[(size_t)NN * DD];  // layer-3 aggregated output
__device__ __align__(16) float g_x[(size_t)NN * DD];    // layer input (x1, x2)
__device__ float g_ssrc[NN * HMAX];
__device__ float g_sdst[NN * HMAX];
__device__ int g_deg[NN];
__device__ int g_cur[NN];
__device__ int g_csr_off[NN + 1];
__device__ int g_csr_src[ETOT];
__device__ int g_off[BB + 2];

// ================= helpers =================
__device__ __forceinline__ uint32_t smem_u32(const void* p) {
    uint32_t a;
    asm("{ .reg .u64 t; cvta.to.shared.u64 t, %1; cvt.u32.u64 %0, t; }" : "=r"(a) : "l"(p));
    return a;
}
#define CP16(sa, g) asm volatile("cp.async.cg.shared.global [%0], [%1], 16;" ::"r"(sa), "l"(g))
#define CP_COMMIT() asm volatile("cp.async.commit_group;" ::: "memory")

__device__ __forceinline__ uint32_t to_tf32(float x) {
    uint32_t u;
    asm("cvt.rna.tf32.f32 %0, %1;" : "=r"(u) : "f"(x));
    return u;
}
__device__ __forceinline__ void mma_tf32(float* d, uint32_t a0, uint32_t a1, uint32_t a2,
                                         uint32_t a3, uint32_t b0, uint32_t b1) {
    asm volatile(
        "mma.sync.aligned.m16n8k8.row.col.f32.tf32.tf32.f32 "
        "{%0,%1,%2,%3}, {%4,%5,%6,%7}, {%8,%9}, {%0,%1,%2,%3};"
        : "+f"(d[0]), "+f"(d[1]), "+f"(d[2]), "+f"(d[3])
        : "r"(a0), "r"(a1), "r"(a2), "r"(a3), "r"(b0), "r"(b1));
}

// ================= tf32 mma.sync GEMM + fused attention logits =================
// g_h[M,384] = A[M,384] @ W[384,384]; also atomically accumulates
// g_ssrc[n,h] += <h_row, a_src[h]>, g_sdst likewise (arrays pre-zeroed).
#define ST_FLOATS (4608 + 4352)
#define GEMM_SMEM (2 * ST_FLOATS * 4)

template <int H, int C>
__global__ __launch_bounds__(256, 2) void gemm_mma(const float* __restrict__ A,
                                                   const float* __restrict__ W,
                                                   const float* __restrict__ asrc,
                                                   const float* __restrict__ adst) {
    extern __shared__ float sm[];
    int tid = threadIdx.x;
    int m0 = blockIdx.y * 128, n0 = blockIdx.x * 128;
    int lane = tid & 31, wid = tid >> 5;
    int wm = wid & 3, wn = wid >> 2;
    int r = lane >> 2, kq = lane & 3;

    float acc[2][8][4];
#pragma unroll
    for (int i = 0; i < 2; i++)
#pragma unroll
        for (int j = 0; j < 8; j++)
#pragma unroll
            for (int q = 0; q < 4; q++) acc[i][j][q] = 0.f;

    auto issue = [&](int c, int st) {
        float* As = sm + st * ST_FLOATS;
        float* Bs = As + 4608;
        int k0 = c * 32;
#pragma unroll
        for (int i = 0; i < 4; i++) {
            int idx = i * 256 + tid;
            int m = idx >> 3, seg = idx & 7;
            int row = m0 + m;
            if (row > NN - 1) row = NN - 1;
            CP16(smem_u32(As + m * 36 + seg * 4), A + (size_t)row * DD + k0 + seg * 4);
        }
#pragma unroll
        for (int i = 0; i < 4; i++) {
            int idx = i * 256 + tid;
            int kr = idx >> 5, seg = idx & 31;
            CP16(smem_u32(Bs + kr * 136 + seg * 4), W + (size_t)(k0 + kr) * DD + n0 + seg * 4);
        }
        CP_COMMIT();
    };

    issue(0, 0);
    for (int c = 0; c < 12; c++) {
        int st = c & 1;
        if (c < 11) {
            issue(c + 1, st ^ 1);
            asm volatile("cp.async.wait_group 1;" ::: "memory");
        } else {
            asm volatile("cp.async.wait_group 0;" ::: "memory");
        }
        __syncthreads();
        const float* As = sm + st * ST_FLOATS;
        const float* Bs = As + 4608;
#pragma unroll
        for (int ks = 0; ks < 4; ks++) {
            int kk = ks * 8;
            uint32_t a[2][4], b[8][2];
#pragma unroll
            for (int mi = 0; mi < 2; mi++) {
                int row = wm * 32 + mi * 16 + r;
                a[mi][0] = to_tf32(As[row * 36 + kk + kq]);
                a[mi][1] = to_tf32(As[(row + 8) * 36 + kk + kq]);
                a[mi][2] = to_tf32(As[row * 36 + kk + kq + 4]);
                a[mi][3] = to_tf32(As[(row + 8) * 36 + kk + kq + 4]);
            }
#pragma unroll
            for (int j = 0; j < 8; j++) {
                int col = wn * 64 + j * 8 + r;
                b[j][0] = to_tf32(Bs[(kk + kq) * 136 + col]);
                b[j][1] = to_tf32(Bs[(kk + kq + 4) * 136 + col]);
            }
#pragma unroll
            for (int mi = 0; mi < 2; mi++)
#pragma unroll
                for (int j = 0; j < 8; j++)
                    mma_tf32(acc[mi][j], a[mi][0], a[mi][1], a[mi][2], a[mi][3], b[j][0], b[j][1]);
        }
        __syncthreads();
    }

    // ---- store h ----
#pragma unroll
    for (int mi = 0; mi < 2; mi++) {
#pragma unroll
        for (int j = 0; j < 8; j++) {
            int row = m0 + wm * 32 + mi * 16 + r;
            int col = n0 + wn * 64 + j * 8 + kq * 2;
            if (row < NN)
                *(float2*)&g_h[(size_t)row * DD + col] = make_float2(acc[mi][j][0], acc[mi][j][1]);
            if (row + 8 < NN)
                *(float2*)&g_h[(size_t)(row + 8) * DD + col] =
                    make_float2(acc[mi][j][2], acc[mi][j][3]);
        }
    }

    // ---- fused attention logits: partial dots over this warp's 64 cols ----
    int n0base = n0 + wn * 64;
    int hlo = n0base / C;
    int hhi = (n0base + 63) / C;
    float ss[4][2] = {}, sd[4][2] = {};
#pragma unroll
    for (int j = 0; j < 8; j++) {
        int colb = n0base + j * 8 + kq * 2;
        int bkt = (n0base + j * 8) / C - hlo;  // head bucket (0 or 1), uniform in quad
#pragma unroll
        for (int q = 0; q < 2; q++) {
            float as = asrc[colb + q], ad = adst[colb + q];
            ss[0][bkt] += acc[0][j][q] * as;
            sd[0][bkt] += acc[0][j][q] * ad;
            ss[1][bkt] += acc[0][j][2 + q] * as;
            sd[1][bkt] += acc[0][j][2 + q] * ad;
            ss[2][bkt] += acc[1][j][q] * as;
            sd[2][bkt] += acc[1][j][q] * ad;
            ss[3][bkt] += acc[1][j][2 + q] * as;
            sd[3][bkt] += acc[1][j][2 + q] * ad;
        }
    }
#pragma unroll
    for (int i = 0; i < 4; i++)
#pragma unroll
        for (int bkt = 0; bkt < 2; bkt++)
#pragma unroll
            for (int o = 1; o < 4; o <<= 1) {
                ss[i][bkt] += __shfl_xor_sync(0xffffffffu, ss[i][bkt], o);
                sd[i][bkt] += __shfl_xor_sync(0xffffffffu, sd[i][bkt], o);
            }
    if (kq == 0) {
        int rows[4] = {m0 + wm * 32 + r, m0 + wm * 32 + r + 8, m0 + wm * 32 + r + 16,
                       m0 + wm * 32 + r + 24};
#pragma unroll
        for (int i = 0; i < 4; i++) {
            if (rows[i] < NN) {
                atomicAdd(&g_ssrc[rows[i] * H + hlo], ss[i][0]);
                atomicAdd(&g_sdst[rows[i] * H + hlo], sd[i][0]);
                if (hhi > hlo) {
                    atomicAdd(&g_ssrc[rows[i] * H + hlo + 1], ss[i][1]);
                    atomicAdd(&g_sdst[rows[i] * H + hlo + 1], sd[i][1]);
                }
            }
        }
    }
}

// ---------------- CSR build ----------------
__global__ void count_kernel(const int* __restrict__ edst) {
    int e = blockIdx.x * blockDim.x + threadIdx.x;
    if (e >= ETOT) return;
    int d = (e < EE) ? edst[e] : (e - EE);
    atomicAdd(&g_deg[d], 1);
}

__global__ void scan_kernel() {
    const int T = 1024;
    const int CH = (NN + T - 1) / T;
    __shared__ int warp_sums[32];
    int t = threadIdx.x;
    int base = t * CH;
    int s = 0;
    for (int i = 0; i < CH; i++) {
        int idx = base + i;
        if (idx < NN) s += g_deg[idx];
    }
    int lane = t & 31, wid = t >> 5;
    int v = s;
#pragma unroll
    for (int o = 1; o < 32; o <<= 1) {
        int u = __shfl_up_sync(0xffffffffu, v, o);
        if (lane >= o) v += u;
    }
    if (lane == 31) warp_sums[wid] = v;
    __syncthreads();
    if (wid == 0) {
        int w = warp_sums[lane];
#pragma unroll
        for (int o = 1; o < 32; o <<= 1) {
            int u = __shfl_up_sync(0xffffffffu, w, o);
            if (lane >= o) w += u;
        }
        warp_sums[lane] = w;
    }
    __syncthreads();
    int excl = v - s + (wid > 0 ? warp_sums[wid - 1] : 0);
    int run = excl;
    for (int i = 0; i < CH; i++) {
        int idx = base + i;
        if (idx < NN) {
            g_csr_off[idx] = run;
            run += g_deg[idx];
        }
    }
    if (t == 0) g_csr_off[NN] = ETOT;
}

__global__ void fill_kernel(const int* __restrict__ esrc, const int* __restrict__ edst) {
    int e = blockIdx.x * blockDim.x + threadIdx.x;
    if (e >= ETOT) return;
    int s, d;
    if (e < EE) {
        s = esrc[e];
        d = edst[e];
    } else {
        s = d = e - EE;
    }
    int slot = g_csr_off[d] + atomicAdd(&g_cur[d], 1);
    g_csr_src[slot] = s;
}

// ---------------- fused softmax-alpha + gather + (bias+LN+ReLU) ----------------
template <int H, int C, bool DO_LN>
__global__ __launch_bounds__(128) void agg_kernel(const float* __restrict__ b,
                                                  const float* __restrict__ gam,
                                                  const float* __restrict__ bet) {
    __shared__ float wbuf[MAXDEG * H];
    __shared__ float invd[H];
    __shared__ float red[4], red2[4];
    int d = blockIdx.x;
    int t = threadIdx.x;
    int beg = g_csr_off[d], end = g_csr_off[d + 1];
    int deg = end - beg;
    const int c0 = t, c1 = t + 128, c2 = t + 256;
    const int h0 = c0 / C, h1 = c1 / C, h2 = c2 / C;
    float n0 = 0.f, n1 = 0.f, n2 = 0.f;

    if (deg <= MAXDEG) {
        int items = deg * H;
        for (int i = t; i < items; i += 128) {
            int p = i / H, h = i - p * H;
            int s = g_csr_src[beg + p];
            float tt = g_ssrc[s * H + h] + g_sdst[d * H + h];
            tt = tt > 0.f ? tt : 0.2f * tt;
            wbuf[i] = __expf(tt);
        }
        __syncthreads();
        if (t < H) {
            float dn = 0.f;
            for (int p = 0; p < deg; p++) dn += wbuf[p * H + t];
            invd[t] = 1.f / (dn + 1e-16f);
        }
        __syncthreads();
        for (int i = t; i < items; i += 128) {
            int h = i - (i / H) * H;
            wbuf[i] *= invd[h];
        }
        __syncthreads();
        int p = 0;
        for (; p + 4 <= deg; p += 4) {
            int s0 = g_csr_src[beg + p], s1 = g_csr_src[beg + p + 1];
            int s2 = g_csr_src[beg + p + 2], s3 = g_csr_src[beg + p + 3];
            const float* r0 = g_h + (size_t)s0 * DD;
            const float* r1 = g_h + (size_t)s1 * DD;
            const float* r2 = g_h + (size_t)s2 * DD;
            const float* r3 = g_h + (size_t)s3 * DD;
            float x00 = r0[c0], x01 = r0[c1], x02 = r0[c2];
            float x10 = r1[c0], x11 = r1[c1], x12 = r1[c2];
            float x20 = r2[c0], x21 = r2[c1], x22 = r2[c2];
            float x30 = r3[c0], x31 = r3[c1], x32 = r3[c2];
            n0 += wbuf[p * H + h0] * x00 + wbuf[(p + 1) * H + h0] * x10 +
                  wbuf[(p + 2) * H + h0] * x20 + wbuf[(p + 3) * H + h0] * x30;
            n1 += wbuf[p * H + h1] * x01 + wbuf[(p + 1) * H + h1] * x11 +
                  wbuf[(p + 2) * H + h1] * x21 + wbuf[(p + 3) * H + h1] * x31;
            n2 += wbuf[p * H + h2] * x02 + wbuf[(p + 1) * H + h2] * x12 +
                  wbuf[(p + 2) * H + h2] * x22 + wbuf[(p + 3) * H + h2] * x32;
        }
        for (; p < deg; p++) {
            int s0 = g_csr_src[beg + p];
            const float* r0 = g_h + (size_t)s0 * DD;
            n0 += wbuf[p * H + h0] * r0[c0];
            n1 += wbuf[p * H + h1] * r0[c1];
            n2 += wbuf[p * H + h2] * r0[c2];
        }
    } else {
        float sd0 = g_sdst[d * H + h0], sd1 = g_sdst[d * H + h1], sd2 = g_sdst[d * H + h2];
        float e0 = 0.f, e1 = 0.f, e2 = 0.f;
        for (int p = beg; p < end; p++) {
            int s = g_csr_src[p];
            const float* hr = g_h + (size_t)s * DD;
            float t0 = g_ssrc[s * H + h0] + sd0;
            float t1 = g_ssrc[s * H + h1] + sd1;
            float t2 = g_ssrc[s * H + h2] + sd2;
            t0 = t0 > 0.f ? t0 : 0.2f * t0;
            t1 = t1 > 0.f ? t1 : 0.2f * t1;
            t2 = t2 > 0.f ? t2 : 0.2f * t2;
            float w0 = __expf(t0), w1 = __expf(t1), w2 = __expf(t2);
            n0 += w0 * hr[c0];
            n1 += w1 * hr[c1];
            n2 += w2 * hr[c2];
            e0 += w0;
            e1 += w1;
            e2 += w2;
        }
        n0 /= (e0 + 1e-16f);
        n1 /= (e1 + 1e-16f);
        n2 /= (e2 + 1e-16f);
    }

    if (DO_LN) {
        float v0 = n0 + b[c0], v1 = n1 + b[c1], v2 = n2 + b[c2];
        float s = v0 + v1 + v2;
#pragma unroll
        for (int o = 16; o; o >>= 1) s += __shfl_down_sync(0xffffffffu, s, o);
        if ((t & 31) == 0) red[t >> 5] = s;
        __syncthreads();
        float mu = (red[0] + red[1] + red[2] + red[3]) * (1.f / 384.f);
        float dv0 = v0 - mu, dv1 = v1 - mu, dv2 = v2 - mu;
        float d2 = dv0 * dv0 + dv1 * dv1 + dv2 * dv2;
#pragma unroll
        for (int o = 16; o; o >>= 1) d2 += __shfl_down_sync(0xffffffffu, d2, o);
        if ((t & 31) == 0) red2[t >> 5] = d2;
        __syncthreads();
        float var = (red2[0] + red2[1] + red2[2] + red2[3]) * (1.f / 384.f);
        float rstd = rsqrtf(var + 1e-5f);
        float y0 = dv0 * rstd * gam[c0] + bet[c0];
        float y1 = dv1 * rstd * gam[c1] + bet[c1];
        float y2 = dv2 * rstd * gam[c2] + bet[c2];
        float* o = g_x + (size_t)d * DD;
        o[c0] = y0 > 0.f ? y0 : 0.f;
        o[c1] = y1 > 0.f ? y1 : 0.f;
        o[c2] = y2 > 0.f ? y2 : 0.f;
    } else {
        float* o = g_out + (size_t)d * DD;
        o[c0] = n0;
        o[c1] = n1;
        o[c2] = n2;
    }
}

// ---------------- batch offsets ----------------
__global__ void offsets_kernel(const int* __restrict__ batch) {
    int g = threadIdx.x;
    if (g > BB) return;
    int lo = 0, hi = NN;
    while (lo < hi) {
        int mid = (lo + hi) >> 1;
        if (batch[mid] < g)
            lo = mid + 1;
        else
            hi = mid;
    }
    g_off[g] = lo;
}

// ---------------- residual + relu(bias) + mean pool (sliced, atomic finish) ----------------
__global__ void pool_kernel(const float* __restrict__ x0, const float* __restrict__ b3,
                            float* __restrict__ out) {
    int g = blockIdx.x, slice = blockIdx.y, c = threadIdx.x;
    int s = g_off[g], e = g_off[g + 1];
    float bias = b3[c], acc = 0.f;
    for (int n = s + slice; n < e; n += 8) {
        float v = g_out[(size_t)n * DD + c] + bias;
        acc += x0[(size_t)n * DD + c] + (v > 0.f ? v : 0.f);
    }
    int cnt = e - s;
    if (cnt < 1) cnt = 1;
    atomicAdd(&out[g * DD + c], acc / (float)cnt);
}

// ---------------- host launch ----------------
extern "C" void kernel_launch(void* const* d_in, const int* in_sizes, int n_in,
                              void* d_out, int out_size) {
    const float* x = (const float*)d_in[0];
    const int* ei = (const int*)d_in[1];
    const int* batch = (const int*)d_in[2];
    const float* W1 = (const float*)d_in[3];
    const float* a1s = (const float*)d_in[4];
    const float* a1d = (const float*)d_in[5];
    const float* b1 = (const float*)d_in[6];
    const float* g1 = (const float*)d_in[7];
    const float* be1 = (const float*)d_in[8];
    const float* W2 = (const float*)d_in[9];
    const float* a2s = (const float*)d_in[10];
    const float* a2d = (const float*)d_in[11];
    const float* b2 = (const float*)d_in[12];
    const float* g2 = (const float*)d_in[13];
    const float* be2 = (const float*)d_in[14];
    const float* W3 = (const float*)d_in[15];
    const float* a3s = (const float*)d_in[16];
    const float* a3d = (const float*)d_in[17];
    const float* b3 = (const float*)d_in[18];
    float* out = (float*)d_out;

    static cudaStream_t aux = nullptr;
    static cudaEvent_t ev0 = nullptr, ev1 = nullptr;
    if (aux == nullptr) {
        cudaStreamCreateWithFlags(&aux, cudaStreamNonBlocking);
        cudaEventCreateWithFlags(&ev0, cudaEventDisableTiming);
        cudaEventCreateWithFlags(&ev1, cudaEventDisableTiming);
    }

    void* pv;
    cudaGetSymbolAddress(&pv, g_deg);
    int* degp = (int*)pv;
    cudaGetSymbolAddress(&pv, g_cur);
    int* curp = (int*)pv;
    cudaGetSymbolAddress(&pv, g_x);
    float* xp = (float*)pv;
    cudaGetSymbolAddress(&pv, g_ssrc);
    float* ssp = (float*)pv;
    cudaGetSymbolAddress(&pv, g_sdst);
    float* sdp = (float*)pv;

    cudaFuncSetAttribute(gemm_mma<4, 96>, cudaFuncAttributeMaxDynamicSharedMemorySize, GEMM_SMEM);
    cudaFuncSetAttribute(gemm_mma<6, 64>, cudaFuncAttributeMaxDynamicSharedMemorySize, GEMM_SMEM);

    const int* esrc = ei;
    const int* edst = ei + EE;
    int eb = (ETOT + 255) / 256;
    dim3 gemm_grid(3, (NN + 127) / 128);

    // ---- fork: CSR build + offsets + output zeroing on aux stream ----
    cudaEventRecord(ev0, 0);
    cudaStreamWaitEvent(aux, ev0, 0);
    cudaMemsetAsync(degp, 0, NN * sizeof(int), aux);
    count_kernel<<<eb, 256, 0, aux>>>(edst);
    scan_kernel<<<1, 1024, 0, aux>>>();
    cudaMemsetAsync(curp, 0, NN * sizeof(int), aux);
    fill_kernel<<<eb, 256, 0, aux>>>(esrc, edst);
    offsets_kernel<<<1, 128, 0, aux>>>(batch);
    cudaMemsetAsync(out, 0, (size_t)BB * DD * sizeof(float), aux);
    cudaEventRecord(ev1, aux);

    // ---- layer 1 (H=4, C=96) ----
    cudaMemsetAsync(ssp, 0, NN * 4 * sizeof(float));
    cudaMemsetAsync(sdp, 0, NN * 4 * sizeof(float));
    gemm_mma<4, 96><<<gemm_grid, 256, GEMM_SMEM>>>(x, W1, a1s, a1d);
    cudaStreamWaitEvent(0, ev1, 0);  // join CSR before aggregation
    agg_kernel<4, 96, true><<<NN, 128>>>(b1, g1, be1);

    // ---- layer 2 (H=4, C=96) ----
    cudaMemsetAsync(ssp, 0, NN * 4 * sizeof(float));
    cudaMemsetAsync(sdp, 0, NN * 4 * sizeof(float));
    gemm_mma<4, 96><<<gemm_grid, 256, GEMM_SMEM>>>(xp, W2, a2s, a2d);
    agg_kernel<4, 96, true><<<NN, 128>>>(b2, g2, be2);

    // ---- layer 3 (H=6, C=64) ----
    cudaMemsetAsync(ssp, 0, NN * 6 * sizeof(float));
    cudaMemsetAsync(sdp, 0, NN * 6 * sizeof(float));
    gemm_mma<6, 64><<<gemm_grid, 256, GEMM_SMEM>>>(xp, W3, a3s, a3d);
    agg_kernel<6, 64, false><<<NN, 128>>>(nullptr, nullptr, nullptr);

    // ---- pooling ----
    pool_kernel<<<dim3(BB, 8), DD>>>(x, b3, out);
}

// round 9
// speedup vs baseline: 6.5433x; 1.0177x over previous
#include <cuda_runtime.h>
#include <cstdint>

#define NN 50000
#define EE 500000
#define DD 384
#define BB 64
#define HMAX 6
#define ETOT (EE + NN)
#define MAXDEG 512

// ---------------- scratch (static device allocations) ----------------
__device__ __align__(16) float g_h[(size_t)NN * DD];    // projected features
__device__ __align__(16) float g_out[(size_t)NN * DD];  // layer-3 aggregated output
__device__ __align__(16) float g_x[(size_t)NN * DD];    // layer input (x1, x2), tf32-rounded
__device__ __align__(16) float g_Wr[3 * DD * DD];       // tf32-rounded weights
__device__ float g_ssrc[3 * NN * HMAX];                 // per-layer slabs
__device__ float g_sdst[3 * NN * HMAX];
__device__ int g_deg[NN];
__device__ int g_cur[NN];
__device__ int g_csr_off[NN + 1];
__device__ int g_csr_src[ETOT];
__device__ int g_off[BB + 2];

// ================= helpers =================
__device__ __forceinline__ uint32_t smem_u32(const void* p) {
    uint32_t a;
    asm("{ .reg .u64 t; cvta.to.shared.u64 t, %1; cvt.u32.u64 %0, t; }" : "=r"(a) : "l"(p));
    return a;
}
#define CP16(sa, g) asm volatile("cp.async.cg.shared.global [%0], [%1], 16;" ::"r"(sa), "l"(g))
#define CP_COMMIT() asm volatile("cp.async.commit_group;" ::: "memory")

__device__ __forceinline__ uint32_t to_tf32(float x) {
    uint32_t u;
    asm("cvt.rna.tf32.f32 %0, %1;" : "=r"(u) : "f"(x));
    return u;
}
__device__ __forceinline__ float tf32f(float x) { return __uint_as_float(to_tf32(x)); }

__device__ __forceinline__ void mma_tf32(float* d, uint32_t a0, uint32_t a1, uint32_t a2,
                                         uint32_t a3, uint32_t b0, uint32_t b1) {
    asm volatile(
        "mma.sync.aligned.m16n8k8.row.col.f32.tf32.tf32.f32 "
        "{%0,%1,%2,%3}, {%4,%5,%6,%7}, {%8,%9}, {%0,%1,%2,%3};"
        : "+f"(d[0]), "+f"(d[1]), "+f"(d[2]), "+f"(d[3])
        : "r"(a0), "r"(a1), "r"(a2), "r"(a3), "r"(b0), "r"(b1));
}

// ================= weight pre-round (tf32 RNA, idempotent) =================
__global__ void round_w(const float* __restrict__ W1, const float* __restrict__ W2,
                        const float* __restrict__ W3) {
    int i4 = blockIdx.x * blockDim.x + threadIdx.x;
    const int NW = DD * DD / 4;
    if (i4 >= 3 * NW) return;
    const float4* src = (i4 < NW) ? (const float4*)W1 : (i4 < 2 * NW) ? (const float4*)W2
                                                                      : (const float4*)W3;
    int o = i4 < NW ? i4 : (i4 < 2 * NW ? i4 - NW : i4 - 2 * NW);
    float4 v = src[o];
    v.x = tf32f(v.x);
    v.y = tf32f(v.y);
    v.z = tf32f(v.z);
    v.w = tf32f(v.w);
    ((float4*)g_Wr)[i4] = v;
}

// ================= tf32 mma.sync GEMM + fused attention logits =================
#define ST_FLOATS (4608 + 4352)
#define GEMM_SMEM (2 * ST_FLOATS * 4)

template <int H, int C, bool CVTA>
__global__ __launch_bounds__(256, 2) void gemm_mma(const float* __restrict__ A,
                                                   const float* __restrict__ W,
                                                   const float* __restrict__ asrc,
                                                   const float* __restrict__ adst,
                                                   float* __restrict__ ssrc,
                                                   float* __restrict__ sdst) {
    extern __shared__ float sm[];
    int tid = threadIdx.x;
    int m0 = blockIdx.y * 128, n0 = blockIdx.x * 128;
    int lane = tid & 31, wid = tid >> 5;
    int wm = wid & 3, wn = wid >> 2;
    int r = lane >> 2, kq = lane & 3;

    float acc[2][8][4];
#pragma unroll
    for (int i = 0; i < 2; i++)
#pragma unroll
        for (int j = 0; j < 8; j++)
#pragma unroll
            for (int q = 0; q < 4; q++) acc[i][j][q] = 0.f;

    auto issue = [&](int c, int st) {
        float* As = sm + st * ST_FLOATS;
        float* Bs = As + 4608;
        int k0 = c * 32;
#pragma unroll
        for (int i = 0; i < 4; i++) {
            int idx = i * 256 + tid;
            int m = idx >> 3, seg = idx & 7;
            int row = m0 + m;
            if (row > NN - 1) row = NN - 1;
            CP16(smem_u32(As + m * 36 + seg * 4), A + (size_t)row * DD + k0 + seg * 4);
        }
#pragma unroll
        for (int i = 0; i < 4; i++) {
            int idx = i * 256 + tid;
            int kr = idx >> 5, seg = idx & 31;
            CP16(smem_u32(Bs + kr * 136 + seg * 4), W + (size_t)(k0 + kr) * DD + n0 + seg * 4);
        }
        CP_COMMIT();
    };

    issue(0, 0);
    for (int c = 0; c < 12; c++) {
        int st = c & 1;
        if (c < 11) {
            issue(c + 1, st ^ 1);
            asm volatile("cp.async.wait_group 1;" ::: "memory");
        } else {
            asm volatile("cp.async.wait_group 0;" ::: "memory");
        }
        __syncthreads();
        const float* As = sm + st * ST_FLOATS;
        const float* Bs = As + 4608;
#pragma unroll
        for (int ks = 0; ks < 4; ks++) {
            int kk = ks * 8;
            uint32_t a[2][4], b[8][2];
#pragma unroll
            for (int mi = 0; mi < 2; mi++) {
                int row = wm * 32 + mi * 16 + r;
                if (CVTA) {
                    a[mi][0] = to_tf32(As[row * 36 + kk + kq]);
                    a[mi][1] = to_tf32(As[(row + 8) * 36 + kk + kq]);
                    a[mi][2] = to_tf32(As[row * 36 + kk + kq + 4]);
                    a[mi][3] = to_tf32(As[(row + 8) * 36 + kk + kq + 4]);
                } else {
                    a[mi][0] = __float_as_uint(As[row * 36 + kk + kq]);
                    a[mi][1] = __float_as_uint(As[(row + 8) * 36 + kk + kq]);
                    a[mi][2] = __float_as_uint(As[row * 36 + kk + kq + 4]);
                    a[mi][3] = __float_as_uint(As[(row + 8) * 36 + kk + kq + 4]);
                }
            }
#pragma unroll
            for (int j = 0; j < 8; j++) {
                int col = wn * 64 + j * 8 + r;
                b[j][0] = __float_as_uint(Bs[(kk + kq) * 136 + col]);
                b[j][1] = __float_as_uint(Bs[(kk + kq + 4) * 136 + col]);
            }
#pragma unroll
            for (int mi = 0; mi < 2; mi++)
#pragma unroll
                for (int j = 0; j < 8; j++)
                    mma_tf32(acc[mi][j], a[mi][0], a[mi][1], a[mi][2], a[mi][3], b[j][0], b[j][1]);
        }
        __syncthreads();
    }

    // ---- store h ----
#pragma unroll
    for (int mi = 0; mi < 2; mi++) {
#pragma unroll
        for (int j = 0; j < 8; j++) {
            int row = m0 + wm * 32 + mi * 16 + r;
            int col = n0 + wn * 64 + j * 8 + kq * 2;
            if (row < NN)
                *(float2*)&g_h[(size_t)row * DD + col] = make_float2(acc[mi][j][0], acc[mi][j][1]);
            if (row + 8 < NN)
                *(float2*)&g_h[(size_t)(row + 8) * DD + col] =
                    make_float2(acc[mi][j][2], acc[mi][j][3]);
        }
    }

    // ---- fused attention logits ----
    int n0base = n0 + wn * 64;
    int hlo = n0base / C;
    int hhi = (n0base + 63) / C;
    float ss[4][2] = {}, sd[4][2] = {};
#pragma unroll
    for (int j = 0; j < 8; j++) {
        int colb = n0base + j * 8 + kq * 2;
        int bkt = (n0base + j * 8) / C - hlo;
#pragma unroll
        for (int q = 0; q < 2; q++) {
            float as = asrc[colb + q], ad = adst[colb + q];
            ss[0][bkt] += acc[0][j][q] * as;
            sd[0][bkt] += acc[0][j][q] * ad;
            ss[1][bkt] += acc[0][j][2 + q] * as;
            sd[1][bkt] += acc[0][j][2 + q] * ad;
            ss[2][bkt] += acc[1][j][q] * as;
            sd[2][bkt] += acc[1][j][q] * ad;
            ss[3][bkt] += acc[1][j][2 + q] * as;
            sd[3][bkt] += acc[1][j][2 + q] * ad;
        }
    }
#pragma unroll
    for (int i = 0; i < 4; i++)
#pragma unroll
        for (int bkt = 0; bkt < 2; bkt++)
#pragma unroll
            for (int o = 1; o < 4; o <<= 1) {
                ss[i][bkt] += __shfl_xor_sync(0xffffffffu, ss[i][bkt], o);
                sd[i][bkt] += __shfl_xor_sync(0xffffffffu, sd[i][bkt], o);
            }
    if (kq == 0) {
        int rows[4] = {m0 + wm * 32 + r, m0 + wm * 32 + r + 8, m0 + wm * 32 + r + 16,
                       m0 + wm * 32 + r + 24};
#pragma unroll
        for (int i = 0; i < 4; i++) {
            if (rows[i] < NN) {
                atomicAdd(&ssrc[rows[i] * H + hlo], ss[i][0]);
                atomicAdd(&sdst[rows[i] * H + hlo], sd[i][0]);
                if (hhi > hlo) {
                    atomicAdd(&ssrc[rows[i] * H + hlo + 1], ss[i][1]);
                    atomicAdd(&sdst[rows[i] * H + hlo + 1], sd[i][1]);
                }
            }
        }
    }
}

// ---------------- CSR build ----------------
__global__ void count_kernel(const int* __restrict__ edst) {
    int e = blockIdx.x * blockDim.x + threadIdx.x;
    if (e >= ETOT) return;
    int d = (e < EE) ? edst[e] : (e - EE);
    atomicAdd(&g_deg[d], 1);
}

__global__ void scan_kernel() {
    const int T = 1024;
    const int CH = (NN + T - 1) / T;
    __shared__ int warp_sums[32];
    int t = threadIdx.x;
    int base = t * CH;
    int s = 0;
    for (int i = 0; i < CH; i++) {
        int idx = base + i;
        if (idx < NN) s += g_deg[idx];
    }
    int lane = t & 31, wid = t >> 5;
    int v = s;
#pragma unroll
    for (int o = 1; o < 32; o <<= 1) {
        int u = __shfl_up_sync(0xffffffffu, v, o);
        if (lane >= o) v += u;
    }
    if (lane == 31) warp_sums[wid] = v;
    __syncthreads();
    if (wid == 0) {
        int w = warp_sums[lane];
#pragma unroll
        for (int o = 1; o < 32; o <<= 1) {
            int u = __shfl_up_sync(0xffffffffu, w, o);
            if (lane >= o) w += u;
        }
        warp_sums[lane] = w;
    }
    __syncthreads();
    int excl = v - s + (wid > 0 ? warp_sums[wid - 1] : 0);
    int run = excl;
    for (int i = 0; i < CH; i++) {
        int idx = base + i;
        if (idx < NN) {
            g_csr_off[idx] = run;
            run += g_deg[idx];
        }
    }
    if (t == 0) g_csr_off[NN] = ETOT;
}

__global__ void fill_kernel(const int* __restrict__ esrc, const int* __restrict__ edst) {
    int e = blockIdx.x * blockDim.x + threadIdx.x;
    if (e >= ETOT) return;
    int s, d;
    if (e < EE) {
        s = esrc[e];
        d = edst[e];
    } else {
        s = d = e - EE;
    }
    int slot = g_csr_off[d] + atomicAdd(&g_cur[d], 1);
    g_csr_src[slot] = s;
}

// ---------------- fused softmax-alpha + gather + (bias+LN+ReLU) ----------------
template <int H, int C, bool DO_LN>
__global__ __launch_bounds__(128) void agg_kernel(const float* __restrict__ b,
                                                  const float* __restrict__ gam,
                                                  const float* __restrict__ bet,
                                                  const float* __restrict__ ssrc,
                                                  const float* __restrict__ sdst) {
    __shared__ float wbuf[MAXDEG * H];
    __shared__ float invd[H];
    __shared__ float red[4], red2[4];
    int d = blockIdx.x;
    int t = threadIdx.x;
    int beg = g_csr_off[d], end = g_csr_off[d + 1];
    int deg = end - beg;
    const int c0 = t, c1 = t + 128, c2 = t + 256;
    const int h0 = c0 / C, h1 = c1 / C, h2 = c2 / C;
    float n0 = 0.f, n1 = 0.f, n2 = 0.f;

    if (deg <= MAXDEG) {
        int items = deg * H;
        for (int i = t; i < items; i += 128) {
            int p = i / H, h = i - p * H;
            int s = g_csr_src[beg + p];
            float tt = ssrc[s * H + h] + sdst[d * H + h];
            tt = tt > 0.f ? tt : 0.2f * tt;
            wbuf[i] = __expf(tt);
        }
        __syncthreads();
        if (t < H) {
            float dn = 0.f;
            for (int p = 0; p < deg; p++) dn += wbuf[p * H + t];
            invd[t] = 1.f / (dn + 1e-16f);
        }
        __syncthreads();
        for (int i = t; i < items; i += 128) {
            int h = i - (i / H) * H;
            wbuf[i] *= invd[h];
        }
        __syncthreads();
        int p = 0;
        for (; p + 4 <= deg; p += 4) {
            int s0 = g_csr_src[beg + p], s1 = g_csr_src[beg + p + 1];
            int s2 = g_csr_src[beg + p + 2], s3 = g_csr_src[beg + p + 3];
            const float* r0 = g_h + (size_t)s0 * DD;
            const float* r1 = g_h + (size_t)s1 * DD;
            const float* r2 = g_h + (size_t)s2 * DD;
            const float* r3 = g_h + (size_t)s3 * DD;
            float x00 = r0[c0], x01 = r0[c1], x02 = r0[c2];
            float x10 = r1[c0], x11 = r1[c1], x12 = r1[c2];
            float x20 = r2[c0], x21 = r2[c1], x22 = r2[c2];
            float x30 = r3[c0], x31 = r3[c1], x32 = r3[c2];
            n0 += wbuf[p * H + h0] * x00 + wbuf[(p + 1) * H + h0] * x10 +
                  wbuf[(p + 2) * H + h0] * x20 + wbuf[(p + 3) * H + h0] * x30;
            n1 += wbuf[p * H + h1] * x01 + wbuf[(p + 1) * H + h1] * x11 +
                  wbuf[(p + 2) * H + h1] * x21 + wbuf[(p + 3) * H + h1] * x31;
            n2 += wbuf[p * H + h2] * x02 + wbuf[(p + 1) * H + h2] * x12 +
                  wbuf[(p + 2) * H + h2] * x22 + wbuf[(p + 3) * H + h2] * x32;
        }
        for (; p < deg; p++) {
            int s0 = g_csr_src[beg + p];
            const float* r0 = g_h + (size_t)s0 * DD;
            n0 += wbuf[p * H + h0] * r0[c0];
            n1 += wbuf[p * H + h1] * r0[c1];
            n2 += wbuf[p * H + h2] * r0[c2];
        }
    } else {
        float sd0 = sdst[d * H + h0], sd1 = sdst[d * H + h1], sd2 = sdst[d * H + h2];
        float e0 = 0.f, e1 = 0.f, e2 = 0.f;
        for (int p = beg; p < end; p++) {
            int s = g_csr_src[p];
            const float* hr = g_h + (size_t)s * DD;
            float t0 = ssrc[s * H + h0] + sd0;
            float t1 = ssrc[s * H + h1] + sd1;
            float t2 = ssrc[s * H + h2] + sd2;
            t0 = t0 > 0.f ? t0 : 0.2f * t0;
            t1 = t1 > 0.f ? t1 : 0.2f * t1;
            t2 = t2 > 0.f ? t2 : 0.2f * t2;
            float w0 = __expf(t0), w1 = __expf(t1), w2 = __expf(t2);
            n0 += w0 * hr[c0];
            n1 += w1 * hr[c1];
            n2 += w2 * hr[c2];
            e0 += w0;
            e1 += w1;
            e2 += w2;
        }
        n0 /= (e0 + 1e-16f);
        n1 /= (e1 + 1e-16f);
        n2 /= (e2 + 1e-16f);
    }

    if (DO_LN) {
        float v0 = n0 + b[c0], v1 = n1 + b[c1], v2 = n2 + b[c2];
        float s = v0 + v1 + v2;
#pragma unroll
        for (int o = 16; o; o >>= 1) s += __shfl_down_sync(0xffffffffu, s, o);
        if ((t & 31) == 0) red[t >> 5] = s;
        __syncthreads();
        float mu = (red[0] + red[1] + red[2] + red[3]) * (1.f / 384.f);
        float dv0 = v0 - mu, dv1 = v1 - mu, dv2 = v2 - mu;
        float d2 = dv0 * dv0 + dv1 * dv1 + dv2 * dv2;
#pragma unroll
        for (int o = 16; o; o >>= 1) d2 += __shfl_down_sync(0xffffffffu, d2, o);
        if ((t & 31) == 0) red2[t >> 5] = d2;
        __syncthreads();
        float var = (red2[0] + red2[1] + red2[2] + red2[3]) * (1.f / 384.f);
        float rstd = rsqrtf(var + 1e-5f);
        float y0 = dv0 * rstd * gam[c0] + bet[c0];
        float y1 = dv1 * rstd * gam[c1] + bet[c1];
        float y2 = dv2 * rstd * gam[c2] + bet[c2];
        // store tf32-rounded (next GEMM consumes raw bits; RNA is what the GEMM
        // would have applied anyway -> bit-identical results)
        float* o = g_x + (size_t)d * DD;
        o[c0] = y0 > 0.f ? tf32f(y0) : 0.f;
        o[c1] = y1 > 0.f ? tf32f(y1) : 0.f;
        o[c2] = y2 > 0.f ? tf32f(y2) : 0.f;
    } else {
        float* o = g_out + (size_t)d * DD;
        o[c0] = n0;
        o[c1] = n1;
        o[c2] = n2;
    }
}

// ---------------- batch offsets ----------------
__global__ void offsets_kernel(const int* __restrict__ batch) {
    int g = threadIdx.x;
    if (g > BB) return;
    int lo = 0, hi = NN;
    while (lo < hi) {
        int mid = (lo + hi) >> 1;
        if (batch[mid] < g)
            lo = mid + 1;
        else
            hi = mid;
    }
    g_off[g] = lo;
}

// ---------------- residual + relu(bias) + mean pool (sliced, atomic finish) ----------------
__global__ void pool_kernel(const float* __restrict__ x0, const float* __restrict__ b3,
                            float* __restrict__ out) {
    int g = blockIdx.x, slice = blockIdx.y, c = threadIdx.x;
    int s = g_off[g], e = g_off[g + 1];
    float bias = b3[c], acc = 0.f;
    for (int n = s + slice; n < e; n += 8) {
        float v = g_out[(size_t)n * DD + c] + bias;
        acc += x0[(size_t)n * DD + c] + (v > 0.f ? v : 0.f);
    }
    int cnt = e - s;
    if (cnt < 1) cnt = 1;
    atomicAdd(&out[g * DD + c], acc / (float)cnt);
}

// ---------------- host launch ----------------
extern "C" void kernel_launch(void* const* d_in, const int* in_sizes, int n_in,
                              void* d_out, int out_size) {
    const float* x = (const float*)d_in[0];
    const int* ei = (const int*)d_in[1];
    const int* batch = (const int*)d_in[2];
    const float* W1 = (const float*)d_in[3];
    const float* a1s = (const float*)d_in[4];
    const float* a1d = (const float*)d_in[5];
    const float* b1 = (const float*)d_in[6];
    const float* g1 = (const float*)d_in[7];
    const float* be1 = (const float*)d_in[8];
    const float* W2 = (const float*)d_in[9];
    const float* a2s = (const float*)d_in[10];
    const float* a2d = (const float*)d_in[11];
    const float* b2 = (const float*)d_in[12];
    const float* g2 = (const float*)d_in[13];
    const float* be2 = (const float*)d_in[14];
    const float* W3 = (const float*)d_in[15];
    const float* a3s = (const float*)d_in[16];
    const float* a3d = (const float*)d_in[17];
    const float* b3 = (const float*)d_in[18];
    float* out = (float*)d_out;

    static cudaStream_t aux = nullptr;
    static cudaEvent_t ev0 = nullptr, ev1 = nullptr;
    if (aux == nullptr) {
        cudaStreamCreateWithFlags(&aux, cudaStreamNonBlocking);
        cudaEventCreateWithFlags(&ev0, cudaEventDisableTiming);
        cudaEventCreateWithFlags(&ev1, cudaEventDisableTiming);
    }

    void* pv;
    cudaGetSymbolAddress(&pv, g_deg);
    int* degp = (int*)pv;
    cudaGetSymbolAddress(&pv, g_cur);
    int* curp = (int*)pv;
    cudaGetSymbolAddress(&pv, g_x);
    float* xp = (float*)pv;
    cudaGetSymbolAddress(&pv, g_ssrc);
    float* ssp = (float*)pv;
    cudaGetSymbolAddress(&pv, g_sdst);
    float* sdp = (float*)pv;
    cudaGetSymbolAddress(&pv, g_Wr);
    float* wr = (float*)pv;

    cudaFuncSetAttribute(gemm_mma<4, 96, true>, cudaFuncAttributeMaxDynamicSharedMemorySize,
                         GEMM_SMEM);
    cudaFuncSetAttribute(gemm_mma<4, 96, false>, cudaFuncAttributeMaxDynamicSharedMemorySize,
                         GEMM_SMEM);
    cudaFuncSetAttribute(gemm_mma<6, 64, false>, cudaFuncAttributeMaxDynamicSharedMemorySize,
                         GEMM_SMEM);

    const int* esrc = ei;
    const int* edst = ei + EE;
    int eb = (ETOT + 255) / 256;
    dim3 gemm_grid(3, (NN + 127) / 128);
    const int SLAB = NN * HMAX;

    // ---- fork: CSR build + offsets + zeroing (layers 2/3 logits, output) ----
    cudaEventRecord(ev0, 0);
    cudaStreamWaitEvent(aux, ev0, 0);
    cudaMemsetAsync(degp, 0, NN * sizeof(int), aux);
    cudaMemsetAsync(ssp + SLAB, 0, 2 * SLAB * sizeof(float), aux);
    cudaMemsetAsync(sdp + SLAB, 0, 2 * SLAB * sizeof(float), aux);
    count_kernel<<<eb, 256, 0, aux>>>(edst);
    scan_kernel<<<1, 1024, 0, aux>>>();
    cudaMemsetAsync(curp, 0, NN * sizeof(int), aux);
    fill_kernel<<<eb, 256, 0, aux>>>(esrc, edst);
    offsets_kernel<<<1, 128, 0, aux>>>(batch);
    cudaMemsetAsync(out, 0, (size_t)BB * DD * sizeof(float), aux);
    cudaEventRecord(ev1, aux);

    // ---- main stream: weight rounding + layer-1 logit zero ----
    cudaMemsetAsync(ssp, 0, NN * 4 * sizeof(float));
    cudaMemsetAsync(sdp, 0, NN * 4 * sizeof(float));
    round_w<<<(3 * DD * DD / 4 + 255) / 256, 256>>>(W1, W2, W3);

    // ---- layer 1 (H=4, C=96) ----
    gemm_mma<4, 96, true><<<gemm_grid, 256, GEMM_SMEM>>>(x, wr, a1s, a1d, ssp, sdp);
    cudaStreamWaitEvent(0, ev1, 0);  // join CSR/zeroing before aggregation
    agg_kernel<4, 96, true><<<NN, 128>>>(b1, g1, be1, ssp, sdp);

    // ---- layer 2 (H=4, C=96) ----
    gemm_mma<4, 96, false><<<gemm_grid, 256, GEMM_SMEM>>>(xp, wr + DD * DD, a2s, a2d, ssp + SLAB,
                                                          sdp + SLAB);
    agg_kernel<4, 96, true><<<NN, 128>>>(b2, g2, be2, ssp + SLAB, sdp + SLAB);

    // ---- layer 3 (H=6, C=64) ----
    gemm_mma<6, 64, false><<<gemm_grid, 256, GEMM_SMEM>>>(xp, wr + 2 * DD * DD, a3s, a3d,
                                                          ssp + 2 * SLAB, sdp + 2 * SLAB);
    agg_kernel<6, 64, false><<<NN, 128>>>(nullptr, nullptr, nullptr, ssp + 2 * SLAB,
                                          sdp + 2 * SLAB);

    // ---- pooling ----
    pool_kernel<<<dim3(BB, 8), DD>>>(x, b3, out);
}